// round 13
// baseline (speedup 1.0000x reference)
#include <cuda_runtime.h>
#include <cuda_fp16.h>
#include <cstdint>

// ============================================================================
// SpikeMLP R13: fixup moved OFF the critical path.
//   default stream: cvt -> gemm1_lif -> gemm2(provisional spikes) -> join ->
//                   flip-correction(out) -> rate
//   side stream   : fixup (R10 variant) runs concurrently with gemm2; records
//                   spike flips (m,hid,sign) instead of patching g_spk.
// ============================================================================

#define STAGES 4
#define BM 128
#define BN 128
#define BK 64
#define STAGE_BYTES (BM * BK * 2)               // 16 KB
#define SMEM_B_OFF  (STAGES * STAGE_BYTES)      // 64 KB
#define SMEM_ALLOC  (2 * STAGES * STAGE_BYTES + 256)
#define HS_STRIDE 136                            // padded f32 row stride

#define FLAG_EPS 4e-3f
#define AMB_EPS  1e-4f
#define FLAG_CAP (1u << 22)
#define FLIP_CAP (1u << 16)

// ---------------- device scratch (no allocation allowed) -------------------
__device__ __align__(256) __half g_xh[16384UL * 512UL];        // 16 MB
__device__ __align__(256) __half g_w1h[2048UL * 512UL];        //  2 MB
__device__ __align__(256) __half g_w2h[512UL * 2048UL];        //  2 MB
__device__ __align__(256) __half g_spk[16384UL * 2048UL];      // 64 MB
__device__ unsigned int g_partial[2048];
__device__ unsigned int g_flags[FLAG_CAP];                      // 16 MB
__device__ unsigned int g_flag_count;
__device__ unsigned int g_flips[FLIP_CAP];
__device__ unsigned int g_flip_count;
__device__ int          g_fix_delta;

// ---------------- PTX helpers ----------------------------------------------
__device__ __forceinline__ uint32_t smem_u32(const void* p) {
    uint32_t a;
    asm("{ .reg .u64 t; cvta.to.shared.u64 t, %1; cvt.u32.u64 %0, t; }"
        : "=r"(a) : "l"(p));
    return a;
}
__device__ __forceinline__ void cp16(uint32_t dst, const void* src) {
    asm volatile("cp.async.cg.shared.global [%0], [%1], 16;\n"
                 :: "r"(dst), "l"(src));
}
__device__ __forceinline__ void ldsm_x4(uint32_t r[4], uint32_t addr) {
    asm volatile("ldmatrix.sync.aligned.m8n8.x4.shared.b16 {%0,%1,%2,%3}, [%4];\n"
                 : "=r"(r[0]), "=r"(r[1]), "=r"(r[2]), "=r"(r[3]) : "r"(addr));
}
__device__ __forceinline__ void mma16816(float c[4], const uint32_t a[4],
                                         const uint32_t* b) {
    asm volatile(
        "mma.sync.aligned.m16n8k16.row.col.f32.f16.f16.f32 "
        "{%0,%1,%2,%3}, {%4,%5,%6,%7}, {%8,%9}, {%0,%1,%2,%3};\n"
        : "+f"(c[0]), "+f"(c[1]), "+f"(c[2]), "+f"(c[3])
        : "r"(a[0]), "r"(a[1]), "r"(a[2]), "r"(a[3]), "r"(b[0]), "r"(b[1]));
}

// ============================================================================
// GEMM1 fused with LIF (tile rows = 4 timesteps x 32 seq of one batch)
// ============================================================================
__global__ __launch_bounds__(256, 1) void gemm1_lif(
    const __half* __restrict__ A, const __half* __restrict__ B)
{
    extern __shared__ uint8_t dynsmem[];
    const uint32_t base = (smem_u32(dynsmem) + 127u) & ~127u;

    const int tid  = threadIdx.x;
    const int wid  = tid >> 5;
    const int lane = tid & 31;
    const int b    = blockIdx.y >> 3;
    const int s0   = (blockIdx.y & 7) * 32;
    const int n0   = blockIdx.x * BN;
    const int warp_m = (wid >> 2) * 64;
    const int warp_n = (wid & 3) * 32;

    int a_rb[4], a_xr[4];
    #pragma unroll
    for (int mt = 0; mt < 4; mt++) {
        const int r = warp_m + mt * 16 + (lane & 15);
        a_rb[mt] = r * 128;
        a_xr[mt] = (r & 7) << 4;
    }
    const int a_c0 = (lane >> 4) * 16;
    int b_rb[2], b_xr[2];
    {
        const int rl = (lane & 7) + ((lane >> 4) << 3);
        #pragma unroll
        for (int p = 0; p < 2; p++) {
            const int r = warp_n + p * 16 + rl;
            b_rb[p] = r * 128;
            b_xr[p] = (r & 7) << 4;
        }
    }
    const int b_c0 = ((lane >> 3) & 1) * 16;

    auto load_chunk = [&](int chunk, int slot) {
        const int k0 = chunk * BK;
        const uint32_t sA = base + slot * STAGE_BYTES;
        const uint32_t sB = base + SMEM_B_OFF + slot * STAGE_BYTES;
        #pragma unroll
        for (int r = 0; r < 4; r++) {
            const int idx = tid + r * 256;
            const int row = idx >> 3;
            const int cb  = (idx & 7) * 16;
            const int ga = b * 1024 + (row >> 5) * 256 + s0 + (row & 31);
            cp16(sA + row * 128 + (cb ^ ((row & 7) << 4)),
                 A + (size_t)ga * 512 + k0 + (cb >> 1));
            cp16(sB + row * 128 + (cb ^ ((row & 7) << 4)),
                 B + (size_t)(n0 + row) * 512 + k0 + (cb >> 1));
        }
    };

    float acc[4][4][4];
    #pragma unroll
    for (int mt = 0; mt < 4; mt++)
        #pragma unroll
        for (int nt = 0; nt < 4; nt++)
            #pragma unroll
            for (int q = 0; q < 4; q++) acc[mt][nt][q] = 0.0f;

    #pragma unroll
    for (int j = 0; j < STAGES - 1; j++) {
        load_chunk(j, j);
        asm volatile("cp.async.commit_group;\n" ::: "memory");
    }

    const int nchunks = 512 / BK;   // 8
    for (int i = 0; i < nchunks; i++) {
        asm volatile("cp.async.wait_group %0;\n" :: "n"(STAGES - 2));
        __syncthreads();
        const int lc = i + STAGES - 1;
        if (lc < nchunks) load_chunk(lc, lc & (STAGES - 1));
        asm volatile("cp.async.commit_group;\n" ::: "memory");

        const uint32_t sA = base + (i & (STAGES - 1)) * STAGE_BYTES;
        const uint32_t sB = base + SMEM_B_OFF + (i & (STAGES - 1)) * STAGE_BYTES;

        uint32_t af[2][4][4], bf[2][2][4];
        #pragma unroll
        for (int mt = 0; mt < 4; mt++)
            ldsm_x4(af[0][mt], sA + a_rb[mt] + ((a_c0) ^ a_xr[mt]));
        #pragma unroll
        for (int p = 0; p < 2; p++)
            ldsm_x4(bf[0][p], sB + b_rb[p] + ((b_c0) ^ b_xr[p]));

        #pragma unroll
        for (int ks = 0; ks < 4; ks++) {
            const int cur = ks & 1, nxt = cur ^ 1;
            if (ks < 3) {
                const int c = (ks + 1) * 32;
                #pragma unroll
                for (int mt = 0; mt < 4; mt++)
                    ldsm_x4(af[nxt][mt], sA + a_rb[mt] + ((c + a_c0) ^ a_xr[mt]));
                #pragma unroll
                for (int p = 0; p < 2; p++)
                    ldsm_x4(bf[nxt][p], sB + b_rb[p] + ((c + b_c0) ^ b_xr[p]));
            }
            #pragma unroll
            for (int mt = 0; mt < 4; mt++)
                #pragma unroll
                for (int nt = 0; nt < 4; nt++)
                    mma16816(acc[mt][nt], af[cur][mt],
                             &bf[cur][nt >> 1][(nt & 1) * 2]);
        }
    }

    // ---- epilogue: acc -> smem f32 tile, in-block LIF scan -----------------
    __syncthreads();
    float* hs = (float*)(dynsmem + ((128 - ((uintptr_t)dynsmem & 127)) & 127));
    #pragma unroll
    for (int mt = 0; mt < 4; mt++) {
        const int row = warp_m + mt * 16 + (lane >> 2);
        #pragma unroll
        for (int nt = 0; nt < 4; nt++) {
            const int col = warp_n + nt * 8 + (lane & 3) * 2;
            *(float2*)&hs[(size_t)row * HS_STRIDE + col] =
                make_float2(acc[mt][nt][0], acc[mt][nt][1]);
            *(float2*)&hs[(size_t)(row + 8) * HS_STRIDE + col] =
                make_float2(acc[mt][nt][2], acc[mt][nt][3]);
        }
    }
    __syncthreads();

    const float beta = (float)(1.0 - 1.0 / 20.0);
    const __half one  = __float2half(1.0f);
    const __half zero = __float2half(0.0f);
    int cnt = 0;

    #pragma unroll
    for (int iter = 0; iter < 16; iter++) {
        const int s   = (iter << 1) | (tid >> 7);
        const int col = tid & 127;
        float v = 0.0f;
        bool flagged = false;
        #pragma unroll
        for (int t = 0; t < 4; t++) {
            const float h = hs[(size_t)(t * 32 + s) * HS_STRIDE + col];
            v = fmaf(beta, v, h);
            flagged |= (fabsf(v - 1.0f) < FLAG_EPS);
            const bool fire = (v > 1.0f);
            g_spk[((size_t)(b * 4 + t) * 256 + s0 + s) * 2048 + n0 + col] =
                fire ? one : zero;
            cnt += fire ? 1 : 0;
            v = fire ? 0.0f : v;
        }
        const unsigned int mask = __ballot_sync(0xFFFFFFFFu, flagged);
        if (flagged) {
            const int leader = __ffs(mask) - 1;
            const int rank   = __popc(mask & ((1u << lane) - 1));
            unsigned int pos = 0;
            if (lane == leader) pos = atomicAdd(&g_flag_count, __popc(mask));
            pos = __shfl_sync(mask, pos, leader);
            const unsigned int nidx =
                (unsigned int)(((b * 256 + s0 + s) << 11) + n0 + col);
            if (pos + rank < FLAG_CAP) g_flags[pos + rank] = nidx;
        }
    }

    #pragma unroll
    for (int o = 16; o; o >>= 1) cnt += __shfl_down_sync(0xFFFFFFFFu, cnt, o);
    __shared__ int warpsum[8];
    if (lane == 0) warpsum[wid] = cnt;
    __syncthreads();
    if (tid == 0) {
        int tot = 0;
        #pragma unroll
        for (int w = 0; w < 8; w++) tot += warpsum[w];
        g_partial[blockIdx.y * 16 + blockIdx.x] = (unsigned int)tot;
    }
}

// ============================================================================
// fp16 NT GEMM (GEMM2)
// ============================================================================
__global__ __launch_bounds__(256, 1) void gemm_f16(
    const __half* __restrict__ A, const __half* __restrict__ B,
    float* __restrict__ C, int ldc, int nchunks, int a_rs, int b_rs)
{
    extern __shared__ uint8_t dynsmem[];
    const uint32_t base = (smem_u32(dynsmem) + 127u) & ~127u;

    const int tid  = threadIdx.x;
    const int wid  = tid >> 5;
    const int lane = tid & 31;
    const int m0   = blockIdx.y * BM;
    const int n0   = blockIdx.x * BN;
    const int warp_m = (wid >> 2) * 64;
    const int warp_n = (wid & 3) * 32;

    int a_rb[4], a_xr[4];
    #pragma unroll
    for (int mt = 0; mt < 4; mt++) {
        const int r = warp_m + mt * 16 + (lane & 15);
        a_rb[mt] = r * 128;
        a_xr[mt] = (r & 7) << 4;
    }
    const int a_c0 = (lane >> 4) * 16;
    int b_rb[2], b_xr[2];
    {
        const int rl = (lane & 7) + ((lane >> 4) << 3);
        #pragma unroll
        for (int p = 0; p < 2; p++) {
            const int r = warp_n + p * 16 + rl;
            b_rb[p] = r * 128;
            b_xr[p] = (r & 7) << 4;
        }
    }
    const int b_c0 = ((lane >> 3) & 1) * 16;

    auto load_chunk = [&](int chunk, int slot) {
        const int k0 = chunk * BK;
        const uint32_t sA = base + slot * STAGE_BYTES;
        const uint32_t sB = base + SMEM_B_OFF + slot * STAGE_BYTES;
        #pragma unroll
        for (int r = 0; r < 4; r++) {
            const int idx = tid + r * 256;
            const int row = idx >> 3;
            const int cb  = (idx & 7) * 16;
            cp16(sA + row * 128 + (cb ^ ((row & 7) << 4)),
                 A + (size_t)(m0 + row) * a_rs + k0 + (cb >> 1));
            cp16(sB + row * 128 + (cb ^ ((row & 7) << 4)),
                 B + (size_t)(n0 + row) * b_rs + k0 + (cb >> 1));
        }
    };

    float acc[4][4][4];
    #pragma unroll
    for (int mt = 0; mt < 4; mt++)
        #pragma unroll
        for (int nt = 0; nt < 4; nt++)
            #pragma unroll
            for (int q = 0; q < 4; q++) acc[mt][nt][q] = 0.0f;

    #pragma unroll
    for (int j = 0; j < STAGES - 1; j++) {
        load_chunk(j, j);
        asm volatile("cp.async.commit_group;\n" ::: "memory");
    }

    for (int i = 0; i < nchunks; i++) {
        asm volatile("cp.async.wait_group %0;\n" :: "n"(STAGES - 2));
        __syncthreads();
        const int lc = i + STAGES - 1;
        if (lc < nchunks) load_chunk(lc, lc & (STAGES - 1));
        asm volatile("cp.async.commit_group;\n" ::: "memory");

        const uint32_t sA = base + (i & (STAGES - 1)) * STAGE_BYTES;
        const uint32_t sB = base + SMEM_B_OFF + (i & (STAGES - 1)) * STAGE_BYTES;

        uint32_t af[2][4][4], bf[2][2][4];
        #pragma unroll
        for (int mt = 0; mt < 4; mt++)
            ldsm_x4(af[0][mt], sA + a_rb[mt] + ((a_c0) ^ a_xr[mt]));
        #pragma unroll
        for (int p = 0; p < 2; p++)
            ldsm_x4(bf[0][p], sB + b_rb[p] + ((b_c0) ^ b_xr[p]));

        #pragma unroll
        for (int ks = 0; ks < 4; ks++) {
            const int cur = ks & 1, nxt = cur ^ 1;
            if (ks < 3) {
                const int c = (ks + 1) * 32;
                #pragma unroll
                for (int mt = 0; mt < 4; mt++)
                    ldsm_x4(af[nxt][mt], sA + a_rb[mt] + ((c + a_c0) ^ a_xr[mt]));
                #pragma unroll
                for (int p = 0; p < 2; p++)
                    ldsm_x4(bf[nxt][p], sB + b_rb[p] + ((c + b_c0) ^ b_xr[p]));
            }
            #pragma unroll
            for (int mt = 0; mt < 4; mt++)
                #pragma unroll
                for (int nt = 0; nt < 4; nt++)
                    mma16816(acc[mt][nt], af[cur][mt],
                             &bf[cur][nt >> 1][(nt & 1) * 2]);
        }
    }

    #pragma unroll
    for (int mt = 0; mt < 4; mt++) {
        #pragma unroll
        for (int nt = 0; nt < 4; nt++) {
            const int row = m0 + warp_m + mt * 16 + (lane >> 2);
            const int col = n0 + warp_n + nt * 8 + (lane & 3) * 2;
            float* c0 = C + (size_t)row * ldc + col;
            float* c1 = C + (size_t)(row + 8) * ldc + col;
            *(float2*)c0 = make_float2(acc[mt][nt][0], acc[mt][nt][1]);
            *(float2*)c1 = make_float2(acc[mt][nt][2], acc[mt][nt][3]);
        }
    }
}

// ============================================================================
// converts (cvt_x also resets per-replay accumulators)
// ============================================================================
__global__ __launch_bounds__(256) void cvt_x(const float* __restrict__ src,
                                             __half* __restrict__ dst)
{
    if (blockIdx.x == 0 && threadIdx.x == 0) {
        g_flag_count = 0;
        g_flip_count = 0;
        g_fix_delta = 0;
    }
    const size_t i = ((size_t)blockIdx.x * 256 + threadIdx.x) * 4;
    const float4 v = *(const float4*)(src + i);
    *(__half2*)(dst + i)     = __floats2half2_rn(v.x, v.y);
    *(__half2*)(dst + i + 2) = __floats2half2_rn(v.z, v.w);
}

__global__ __launch_bounds__(256) void cvt_w(
    const float* __restrict__ w1, __half* __restrict__ w1d,
    const float* __restrict__ w2, __half* __restrict__ w2d)
{
    const int half_grid = (int)gridDim.x >> 1;
    const bool second = blockIdx.x >= half_grid;
    const float* src = second ? w2 : w1;
    __half* dst = second ? w2d : w1d;
    const size_t i =
        ((size_t)(blockIdx.x - (second ? half_grid : 0)) * 256 + threadIdx.x) * 4;
    const float4 v = *(const float4*)(src + i);
    *(__half2*)(dst + i)     = __floats2half2_rn(v.x, v.y);
    *(__half2*)(dst + i + 2) = __floats2half2_rn(v.z, v.w);
}

// ============================================================================
// Two-phase fixup (R10 variant), flip-recording: reads provisional g_spk
// (read-only), records (m,hid,sign) flips instead of patching spikes.
// ============================================================================
__global__ __launch_bounds__(256) void fixup_kernel(
    const float* __restrict__ x, const float* __restrict__ w1)
{
    __shared__ float s_w[8][512];
    __shared__ float s_x[8][512];

    const unsigned int n = min(g_flag_count, (unsigned int)FLAG_CAP);
    const int lane = threadIdx.x & 31;
    const int wib  = threadIdx.x >> 5;
    const unsigned int warp = (blockIdx.x * 256 + threadIdx.x) >> 5;
    const unsigned int nwarps = (gridDim.x * 256) >> 5;
    int delta = 0;

    const float beta = (float)(1.0 - 1.0 / 20.0);

    for (unsigned int i = warp; i < n; i += nwarps) {
        const unsigned int idx = g_flags[i];
        const int    hid = (int)(idx & 2047u);
        const size_t bs  = idx >> 11;
        const size_t b   = bs >> 8;
        const size_t s   = bs & 255;
        const size_t bse = ((b * 4) * 256 + s) * 2048 + hid;
        const size_t ts  = 256UL * 2048UL;

        const float4* wrow = (const float4*)(w1 + (size_t)hid * 512);
        float w[16];
        #pragma unroll
        for (int j = 0; j < 4; j++) {
            const float4 wv = wrow[lane + j * 32];
            w[j * 4 + 0] = wv.x; w[j * 4 + 1] = wv.y;
            w[j * 4 + 2] = wv.z; w[j * 4 + 3] = wv.w;
        }

        // phase A: butterfly dots
        float accs[4];
        #pragma unroll
        for (int t = 0; t < 4; t++) {
            const float4* xrow =
                (const float4*)(x + (((b * 4 + t) * 256 + s) << 9));
            float a = 0.0f;
            #pragma unroll
            for (int j = 0; j < 4; j++) {
                const float4 xv = xrow[lane + j * 32];
                a = fmaf(xv.x, w[j * 4 + 0], a);
                a = fmaf(xv.y, w[j * 4 + 1], a);
                a = fmaf(xv.z, w[j * 4 + 2], a);
                a = fmaf(xv.w, w[j * 4 + 3], a);
            }
            #pragma unroll
            for (int o = 16; o; o >>= 1)
                a += __shfl_xor_sync(0xFFFFFFFFu, a, o);
            accs[t] = a;
        }

        // ambiguity test (warp-uniform)
        bool amb = false;
        {
            float v = 0.0f;
            #pragma unroll
            for (int t = 0; t < 4; t++) {
                v = fmaf(beta, v, accs[t]);
                amb |= (fabsf(v - 1.0f) < AMB_EPS);
                v = (v > 1.0f) ? 0.0f : v;
            }
        }

        if (amb) {
            // phase B: smem-staged exact sequential recompute
            #pragma unroll
            for (int j = 0; j < 4; j++)
                *(float4*)&s_w[wib][(lane + j * 32) * 4] = wrow[lane + j * 32];
            #pragma unroll
            for (int t = 0; t < 4; t++) {
                const float4* xrow =
                    (const float4*)(x + (((b * 4 + t) * 256 + s) << 9));
                #pragma unroll
                for (int j = 0; j < 4; j++)
                    *(float4*)&s_x[wib][(lane + j * 32) * 4] = xrow[lane + j * 32];
                __syncwarp();
                if (lane == 0) {
                    float a = 0.0f;
                    #pragma unroll 8
                    for (int k = 0; k < 512; k++)
                        a = fmaf(s_x[wib][k], s_w[wib][k], a);
                    accs[t] = a;
                }
                __syncwarp();
            }
        }

        if (lane == 0) {
            float v = 0.0f;
            #pragma unroll
            for (int t = 0; t < 4; t++) {
                v = fmaf(beta, v, accs[t]);
                const bool fire = (v > 1.0f);
                const __half old = g_spk[bse + (size_t)t * ts];
                const bool oldf = (__half2float(old) > 0.5f);
                if (fire != oldf) {
                    delta += fire ? 1 : -1;
                    const unsigned int m =
                        (unsigned int)((b * 4 + t) * 256 + s);
                    const unsigned int enc =
                        m | ((unsigned int)hid << 14) | (fire ? (1u << 25) : 0u);
                    const unsigned int pos = atomicAdd(&g_flip_count, 1u);
                    if (pos < FLIP_CAP) g_flips[pos] = enc;
                }
                v = fire ? 0.0f : v;
            }
        }
    }

    #pragma unroll
    for (int o = 16; o; o >>= 1) delta += __shfl_down_sync(0xFFFFFFFFu, delta, o);
    __shared__ int wsum[8];
    if (lane == 0) wsum[wib] = delta;
    __syncthreads();
    if (threadIdx.x == 0) {
        int tot = 0;
        #pragma unroll
        for (int w = 0; w < 8; w++) tot += wsum[w];
        if (tot != 0) atomicAdd(&g_fix_delta, tot);
    }
}

// ============================================================================
// Flip correction: out[m, :] += sign * w2[:, hid]  (one block per flip)
// ============================================================================
__global__ __launch_bounds__(512) void correct_kernel(
    const float* __restrict__ w2, float* __restrict__ out)
{
    const unsigned int n = min(g_flip_count, (unsigned int)FLIP_CAP);
    for (unsigned int f = blockIdx.x; f < n; f += gridDim.x) {
        const unsigned int e = g_flips[f];
        const unsigned int m   = e & 0x3FFFu;
        const unsigned int hid = (e >> 14) & 0x7FFu;
        const float sgn = (e & (1u << 25)) ? 1.0f : -1.0f;
        const int d = threadIdx.x;            // 512 threads, one d each
        atomicAdd(&out[(size_t)m * 512 + d],
                  sgn * w2[(size_t)d * 2048 + hid]);
    }
}

__global__ __launch_bounds__(1024) void rate_kernel(float* __restrict__ out_rate)
{
    long long s = 0;
    for (int i = threadIdx.x; i < 2048; i += 1024) s += g_partial[i];
    #pragma unroll
    for (int o = 16; o; o >>= 1) s += __shfl_down_sync(0xFFFFFFFFu, s, o);
    __shared__ long long sh[32];
    if ((threadIdx.x & 31) == 0) sh[threadIdx.x >> 5] = s;
    __syncthreads();
    if (threadIdx.x == 0) {
        long long tot = 0;
        #pragma unroll
        for (int w = 0; w < 32; w++) tot += sh[w];
        tot += g_fix_delta;
        *out_rate = (float)((double)tot / 33554432.0);
    }
}

// ============================================================================
extern "C" void kernel_launch(void* const* d_in, const int* in_sizes, int n_in,
                              void* d_out, int out_size)
{
    const float* x  = (const float*)d_in[0];
    const float* w1 = (const float*)d_in[1];
    const float* w2 = (const float*)d_in[2];
    float* out = (float*)d_out;

    __half *xh, *w1h, *w2h, *spk;
    cudaGetSymbolAddress((void**)&xh,  g_xh);
    cudaGetSymbolAddress((void**)&w1h, g_w1h);
    cudaGetSymbolAddress((void**)&w2h, g_w2h);
    cudaGetSymbolAddress((void**)&spk, g_spk);

    cudaFuncSetAttribute(gemm1_lif, cudaFuncAttributeMaxDynamicSharedMemorySize,
                         SMEM_ALLOC);
    cudaFuncSetAttribute(gemm_f16, cudaFuncAttributeMaxDynamicSharedMemorySize,
                         SMEM_ALLOC);

    // side stream + fork/join events, created once on the first (uncaptured)
    // correctness call; reused under graph capture (fork-join edges only).
    static cudaStream_t s_fix = nullptr;
    static cudaEvent_t  e_fork = nullptr, e_join = nullptr;
    if (s_fix == nullptr) {
        cudaStreamCreateWithFlags(&s_fix, cudaStreamNonBlocking);
        cudaEventCreateWithFlags(&e_fork, cudaEventDisableTiming);
        cudaEventCreateWithFlags(&e_join, cudaEventDisableTiming);
    }

    cvt_x<<<8192, 256>>>(x, xh);
    cvt_w<<<2048, 256>>>(w1, w1h, w2, w2h);

    // GEMM1 + LIF fused (provisional spikes + flag list)
    gemm1_lif<<<dim3(16, 128), 256, SMEM_ALLOC>>>(xh, w1h);

    // fork: fixup runs concurrently with GEMM2
    cudaEventRecord(e_fork, 0);
    cudaStreamWaitEvent(s_fix, e_fork, 0);
    fixup_kernel<<<1184, 256, 0, s_fix>>>(x, w1);
    cudaEventRecord(e_join, s_fix);

    // GEMM2 on provisional spikes (default stream, concurrent with fixup)
    gemm_f16<<<dim3(512 / BN, 16384 / BM), 256, SMEM_ALLOC>>>(
        spk, w2h, out, 512, 2048 / BK, 2048, 2048);

    // join, then apply sparse flip corrections and rate
    cudaStreamWaitEvent(0, e_join, 0);
    correct_kernel<<<64, 512>>>(w2, out);
    rate_kernel<<<1, 1024>>>(out + (out_size - 1));
}

// round 14
// speedup vs baseline: 1.1586x; 1.1586x over previous
#include <cuda_runtime.h>
#include <cuda_fp16.h>
#include <cstdint>

// ============================================================================
// SpikeMLP R14 = R10 pipeline + fixup split into two kernels:
//   fixup_a: phase A only (butterfly dots, w cached in regs), 4 CTAs/SM via
//            launch_bounds(256,4); ambiguous neurons deferred to a list.
//   fixup_b: warp-per-ambiguous-neuron exact sequential fp32 recompute
//            (smem-staged), patches spikes + delta.
// Decisions identical to R10 (phase A applies only order-invariant decisions).
// ============================================================================

#define STAGES 4
#define BM 128
#define BN 128
#define BK 64
#define STAGE_BYTES (BM * BK * 2)               // 16 KB
#define SMEM_B_OFF  (STAGES * STAGE_BYTES)      // 64 KB
#define SMEM_ALLOC  (2 * STAGES * STAGE_BYTES + 256)
#define HS_STRIDE 136                            // padded f32 row stride

#define FLAG_EPS 4e-3f
#define AMB_EPS  1e-4f
#define FLAG_CAP (1u << 22)
#define AMB_CAP  (1u << 20)

// ---------------- device scratch (no allocation allowed) -------------------
__device__ __align__(256) __half g_xh[16384UL * 512UL];        // 16 MB
__device__ __align__(256) __half g_w1h[2048UL * 512UL];        //  2 MB
__device__ __align__(256) __half g_w2h[512UL * 2048UL];        //  2 MB
__device__ __align__(256) __half g_spk[16384UL * 2048UL];      // 64 MB
__device__ unsigned int g_partial[2048];
__device__ unsigned int g_flags[FLAG_CAP];                      // 16 MB
__device__ unsigned int g_flag_count;
__device__ unsigned int g_amb[AMB_CAP];                         //  4 MB
__device__ unsigned int g_amb_count;
__device__ int          g_fix_delta;

// ---------------- PTX helpers ----------------------------------------------
__device__ __forceinline__ uint32_t smem_u32(const void* p) {
    uint32_t a;
    asm("{ .reg .u64 t; cvta.to.shared.u64 t, %1; cvt.u32.u64 %0, t; }"
        : "=r"(a) : "l"(p));
    return a;
}
__device__ __forceinline__ void cp16(uint32_t dst, const void* src) {
    asm volatile("cp.async.cg.shared.global [%0], [%1], 16;\n"
                 :: "r"(dst), "l"(src));
}
__device__ __forceinline__ void ldsm_x4(uint32_t r[4], uint32_t addr) {
    asm volatile("ldmatrix.sync.aligned.m8n8.x4.shared.b16 {%0,%1,%2,%3}, [%4];\n"
                 : "=r"(r[0]), "=r"(r[1]), "=r"(r[2]), "=r"(r[3]) : "r"(addr));
}
__device__ __forceinline__ void mma16816(float c[4], const uint32_t a[4],
                                         const uint32_t* b) {
    asm volatile(
        "mma.sync.aligned.m16n8k16.row.col.f32.f16.f16.f32 "
        "{%0,%1,%2,%3}, {%4,%5,%6,%7}, {%8,%9}, {%0,%1,%2,%3};\n"
        : "+f"(c[0]), "+f"(c[1]), "+f"(c[2]), "+f"(c[3])
        : "r"(a[0]), "r"(a[1]), "r"(a[2]), "r"(a[3]), "r"(b[0]), "r"(b[1]));
}

// ============================================================================
// GEMM1 fused with LIF (tile rows = 4 timesteps x 32 seq of one batch)
// ============================================================================
__global__ __launch_bounds__(256, 1) void gemm1_lif(
    const __half* __restrict__ A, const __half* __restrict__ B)
{
    extern __shared__ uint8_t dynsmem[];
    const uint32_t base = (smem_u32(dynsmem) + 127u) & ~127u;

    const int tid  = threadIdx.x;
    const int wid  = tid >> 5;
    const int lane = tid & 31;
    const int b    = blockIdx.y >> 3;
    const int s0   = (blockIdx.y & 7) * 32;
    const int n0   = blockIdx.x * BN;
    const int warp_m = (wid >> 2) * 64;
    const int warp_n = (wid & 3) * 32;

    int a_rb[4], a_xr[4];
    #pragma unroll
    for (int mt = 0; mt < 4; mt++) {
        const int r = warp_m + mt * 16 + (lane & 15);
        a_rb[mt] = r * 128;
        a_xr[mt] = (r & 7) << 4;
    }
    const int a_c0 = (lane >> 4) * 16;
    int b_rb[2], b_xr[2];
    {
        const int rl = (lane & 7) + ((lane >> 4) << 3);
        #pragma unroll
        for (int p = 0; p < 2; p++) {
            const int r = warp_n + p * 16 + rl;
            b_rb[p] = r * 128;
            b_xr[p] = (r & 7) << 4;
        }
    }
    const int b_c0 = ((lane >> 3) & 1) * 16;

    auto load_chunk = [&](int chunk, int slot) {
        const int k0 = chunk * BK;
        const uint32_t sA = base + slot * STAGE_BYTES;
        const uint32_t sB = base + SMEM_B_OFF + slot * STAGE_BYTES;
        #pragma unroll
        for (int r = 0; r < 4; r++) {
            const int idx = tid + r * 256;
            const int row = idx >> 3;
            const int cb  = (idx & 7) * 16;
            const int ga = b * 1024 + (row >> 5) * 256 + s0 + (row & 31);
            cp16(sA + row * 128 + (cb ^ ((row & 7) << 4)),
                 A + (size_t)ga * 512 + k0 + (cb >> 1));
            cp16(sB + row * 128 + (cb ^ ((row & 7) << 4)),
                 B + (size_t)(n0 + row) * 512 + k0 + (cb >> 1));
        }
    };

    float acc[4][4][4];
    #pragma unroll
    for (int mt = 0; mt < 4; mt++)
        #pragma unroll
        for (int nt = 0; nt < 4; nt++)
            #pragma unroll
            for (int q = 0; q < 4; q++) acc[mt][nt][q] = 0.0f;

    #pragma unroll
    for (int j = 0; j < STAGES - 1; j++) {
        load_chunk(j, j);
        asm volatile("cp.async.commit_group;\n" ::: "memory");
    }

    const int nchunks = 512 / BK;   // 8
    for (int i = 0; i < nchunks; i++) {
        asm volatile("cp.async.wait_group %0;\n" :: "n"(STAGES - 2));
        __syncthreads();
        const int lc = i + STAGES - 1;
        if (lc < nchunks) load_chunk(lc, lc & (STAGES - 1));
        asm volatile("cp.async.commit_group;\n" ::: "memory");

        const uint32_t sA = base + (i & (STAGES - 1)) * STAGE_BYTES;
        const uint32_t sB = base + SMEM_B_OFF + (i & (STAGES - 1)) * STAGE_BYTES;

        uint32_t af[2][4][4], bf[2][2][4];
        #pragma unroll
        for (int mt = 0; mt < 4; mt++)
            ldsm_x4(af[0][mt], sA + a_rb[mt] + ((a_c0) ^ a_xr[mt]));
        #pragma unroll
        for (int p = 0; p < 2; p++)
            ldsm_x4(bf[0][p], sB + b_rb[p] + ((b_c0) ^ b_xr[p]));

        #pragma unroll
        for (int ks = 0; ks < 4; ks++) {
            const int cur = ks & 1, nxt = cur ^ 1;
            if (ks < 3) {
                const int c = (ks + 1) * 32;
                #pragma unroll
                for (int mt = 0; mt < 4; mt++)
                    ldsm_x4(af[nxt][mt], sA + a_rb[mt] + ((c + a_c0) ^ a_xr[mt]));
                #pragma unroll
                for (int p = 0; p < 2; p++)
                    ldsm_x4(bf[nxt][p], sB + b_rb[p] + ((c + b_c0) ^ b_xr[p]));
            }
            #pragma unroll
            for (int mt = 0; mt < 4; mt++)
                #pragma unroll
                for (int nt = 0; nt < 4; nt++)
                    mma16816(acc[mt][nt], af[cur][mt],
                             &bf[cur][nt >> 1][(nt & 1) * 2]);
        }
    }

    // ---- epilogue: acc -> smem f32 tile, in-block LIF scan -----------------
    __syncthreads();
    float* hs = (float*)(dynsmem + ((128 - ((uintptr_t)dynsmem & 127)) & 127));
    #pragma unroll
    for (int mt = 0; mt < 4; mt++) {
        const int row = warp_m + mt * 16 + (lane >> 2);
        #pragma unroll
        for (int nt = 0; nt < 4; nt++) {
            const int col = warp_n + nt * 8 + (lane & 3) * 2;
            *(float2*)&hs[(size_t)row * HS_STRIDE + col] =
                make_float2(acc[mt][nt][0], acc[mt][nt][1]);
            *(float2*)&hs[(size_t)(row + 8) * HS_STRIDE + col] =
                make_float2(acc[mt][nt][2], acc[mt][nt][3]);
        }
    }
    __syncthreads();

    const float beta = (float)(1.0 - 1.0 / 20.0);
    const __half one  = __float2half(1.0f);
    const __half zero = __float2half(0.0f);
    int cnt = 0;

    #pragma unroll
    for (int iter = 0; iter < 16; iter++) {
        const int s   = (iter << 1) | (tid >> 7);
        const int col = tid & 127;
        float v = 0.0f;
        bool flagged = false;
        #pragma unroll
        for (int t = 0; t < 4; t++) {
            const float h = hs[(size_t)(t * 32 + s) * HS_STRIDE + col];
            v = fmaf(beta, v, h);
            flagged |= (fabsf(v - 1.0f) < FLAG_EPS);
            const bool fire = (v > 1.0f);
            g_spk[((size_t)(b * 4 + t) * 256 + s0 + s) * 2048 + n0 + col] =
                fire ? one : zero;
            cnt += fire ? 1 : 0;
            v = fire ? 0.0f : v;
        }
        const unsigned int mask = __ballot_sync(0xFFFFFFFFu, flagged);
        if (flagged) {
            const int leader = __ffs(mask) - 1;
            const int rank   = __popc(mask & ((1u << lane) - 1));
            unsigned int pos = 0;
            if (lane == leader) pos = atomicAdd(&g_flag_count, __popc(mask));
            pos = __shfl_sync(mask, pos, leader);
            const unsigned int nidx =
                (unsigned int)(((b * 256 + s0 + s) << 11) + n0 + col);
            if (pos + rank < FLAG_CAP) g_flags[pos + rank] = nidx;
        }
    }

    #pragma unroll
    for (int o = 16; o; o >>= 1) cnt += __shfl_down_sync(0xFFFFFFFFu, cnt, o);
    __shared__ int warpsum[8];
    if (lane == 0) warpsum[wid] = cnt;
    __syncthreads();
    if (tid == 0) {
        int tot = 0;
        #pragma unroll
        for (int w = 0; w < 8; w++) tot += warpsum[w];
        g_partial[blockIdx.y * 16 + blockIdx.x] = (unsigned int)tot;
    }
}

// ============================================================================
// fp16 NT GEMM (GEMM2)
// ============================================================================
__global__ __launch_bounds__(256, 1) void gemm_f16(
    const __half* __restrict__ A, const __half* __restrict__ B,
    float* __restrict__ C, int ldc, int nchunks, int a_rs, int b_rs)
{
    extern __shared__ uint8_t dynsmem[];
    const uint32_t base = (smem_u32(dynsmem) + 127u) & ~127u;

    const int tid  = threadIdx.x;
    const int wid  = tid >> 5;
    const int lane = tid & 31;
    const int m0   = blockIdx.y * BM;
    const int n0   = blockIdx.x * BN;
    const int warp_m = (wid >> 2) * 64;
    const int warp_n = (wid & 3) * 32;

    int a_rb[4], a_xr[4];
    #pragma unroll
    for (int mt = 0; mt < 4; mt++) {
        const int r = warp_m + mt * 16 + (lane & 15);
        a_rb[mt] = r * 128;
        a_xr[mt] = (r & 7) << 4;
    }
    const int a_c0 = (lane >> 4) * 16;
    int b_rb[2], b_xr[2];
    {
        const int rl = (lane & 7) + ((lane >> 4) << 3);
        #pragma unroll
        for (int p = 0; p < 2; p++) {
            const int r = warp_n + p * 16 + rl;
            b_rb[p] = r * 128;
            b_xr[p] = (r & 7) << 4;
        }
    }
    const int b_c0 = ((lane >> 3) & 1) * 16;

    auto load_chunk = [&](int chunk, int slot) {
        const int k0 = chunk * BK;
        const uint32_t sA = base + slot * STAGE_BYTES;
        const uint32_t sB = base + SMEM_B_OFF + slot * STAGE_BYTES;
        #pragma unroll
        for (int r = 0; r < 4; r++) {
            const int idx = tid + r * 256;
            const int row = idx >> 3;
            const int cb  = (idx & 7) * 16;
            cp16(sA + row * 128 + (cb ^ ((row & 7) << 4)),
                 A + (size_t)(m0 + row) * a_rs + k0 + (cb >> 1));
            cp16(sB + row * 128 + (cb ^ ((row & 7) << 4)),
                 B + (size_t)(n0 + row) * b_rs + k0 + (cb >> 1));
        }
    };

    float acc[4][4][4];
    #pragma unroll
    for (int mt = 0; mt < 4; mt++)
        #pragma unroll
        for (int nt = 0; nt < 4; nt++)
            #pragma unroll
            for (int q = 0; q < 4; q++) acc[mt][nt][q] = 0.0f;

    #pragma unroll
    for (int j = 0; j < STAGES - 1; j++) {
        load_chunk(j, j);
        asm volatile("cp.async.commit_group;\n" ::: "memory");
    }

    for (int i = 0; i < nchunks; i++) {
        asm volatile("cp.async.wait_group %0;\n" :: "n"(STAGES - 2));
        __syncthreads();
        const int lc = i + STAGES - 1;
        if (lc < nchunks) load_chunk(lc, lc & (STAGES - 1));
        asm volatile("cp.async.commit_group;\n" ::: "memory");

        const uint32_t sA = base + (i & (STAGES - 1)) * STAGE_BYTES;
        const uint32_t sB = base + SMEM_B_OFF + (i & (STAGES - 1)) * STAGE_BYTES;

        uint32_t af[2][4][4], bf[2][2][4];
        #pragma unroll
        for (int mt = 0; mt < 4; mt++)
            ldsm_x4(af[0][mt], sA + a_rb[mt] + ((a_c0) ^ a_xr[mt]));
        #pragma unroll
        for (int p = 0; p < 2; p++)
            ldsm_x4(bf[0][p], sB + b_rb[p] + ((b_c0) ^ b_xr[p]));

        #pragma unroll
        for (int ks = 0; ks < 4; ks++) {
            const int cur = ks & 1, nxt = cur ^ 1;
            if (ks < 3) {
                const int c = (ks + 1) * 32;
                #pragma unroll
                for (int mt = 0; mt < 4; mt++)
                    ldsm_x4(af[nxt][mt], sA + a_rb[mt] + ((c + a_c0) ^ a_xr[mt]));
                #pragma unroll
                for (int p = 0; p < 2; p++)
                    ldsm_x4(bf[nxt][p], sB + b_rb[p] + ((c + b_c0) ^ b_xr[p]));
            }
            #pragma unroll
            for (int mt = 0; mt < 4; mt++)
                #pragma unroll
                for (int nt = 0; nt < 4; nt++)
                    mma16816(acc[mt][nt], af[cur][mt],
                             &bf[cur][nt >> 1][(nt & 1) * 2]);
        }
    }

    #pragma unroll
    for (int mt = 0; mt < 4; mt++) {
        #pragma unroll
        for (int nt = 0; nt < 4; nt++) {
            const int row = m0 + warp_m + mt * 16 + (lane >> 2);
            const int col = n0 + warp_n + nt * 8 + (lane & 3) * 2;
            float* c0 = C + (size_t)row * ldc + col;
            float* c1 = C + (size_t)(row + 8) * ldc + col;
            *(float2*)c0 = make_float2(acc[mt][nt][0], acc[mt][nt][1]);
            *(float2*)c1 = make_float2(acc[mt][nt][2], acc[mt][nt][3]);
        }
    }
}

// ============================================================================
// converts (cvt_x also resets per-replay accumulators)
// ============================================================================
__global__ __launch_bounds__(256) void cvt_x(const float* __restrict__ src,
                                             __half* __restrict__ dst)
{
    if (blockIdx.x == 0 && threadIdx.x == 0) {
        g_flag_count = 0;
        g_amb_count = 0;
        g_fix_delta = 0;
    }
    const size_t i = ((size_t)blockIdx.x * 256 + threadIdx.x) * 4;
    const float4 v = *(const float4*)(src + i);
    *(__half2*)(dst + i)     = __floats2half2_rn(v.x, v.y);
    *(__half2*)(dst + i + 2) = __floats2half2_rn(v.z, v.w);
}

__global__ __launch_bounds__(256) void cvt_w(
    const float* __restrict__ w1, __half* __restrict__ w1d,
    const float* __restrict__ w2, __half* __restrict__ w2d)
{
    const int half_grid = (int)gridDim.x >> 1;
    const bool second = blockIdx.x >= half_grid;
    const float* src = second ? w2 : w1;
    __half* dst = second ? w2d : w1d;
    const size_t i =
        ((size_t)(blockIdx.x - (second ? half_grid : 0)) * 256 + threadIdx.x) * 4;
    const float4 v = *(const float4*)(src + i);
    *(__half2*)(dst + i)     = __floats2half2_rn(v.x, v.y);
    *(__half2*)(dst + i + 2) = __floats2half2_rn(v.z, v.w);
}

// ============================================================================
// fixup_a: phase A only (R10 arithmetic), high occupancy. Ambiguous neurons
// are deferred to g_amb; confident decisions are applied directly.
// ============================================================================
__global__ __launch_bounds__(256, 4) void fixup_a(
    const float* __restrict__ x, const float* __restrict__ w1)
{
    const unsigned int n = min(g_flag_count, (unsigned int)FLAG_CAP);
    const int lane = threadIdx.x & 31;
    const unsigned int warp = (blockIdx.x * 256 + threadIdx.x) >> 5;
    const unsigned int nwarps = (gridDim.x * 256) >> 5;
    int delta = 0;

    const float beta = (float)(1.0 - 1.0 / 20.0);
    const __half one  = __float2half(1.0f);
    const __half zero = __float2half(0.0f);

    for (unsigned int i = warp; i < n; i += nwarps) {
        const unsigned int idx = g_flags[i];
        const int    hid = (int)(idx & 2047u);
        const size_t bs  = idx >> 11;
        const size_t b   = bs >> 8;
        const size_t s   = bs & 255;
        const size_t bse = ((b * 4) * 256 + s) * 2048 + hid;
        const size_t ts  = 256UL * 2048UL;

        const float4* wrow = (const float4*)(w1 + (size_t)hid * 512);
        float w[16];
        #pragma unroll
        for (int j = 0; j < 4; j++) {
            const float4 wv = wrow[lane + j * 32];
            w[j * 4 + 0] = wv.x; w[j * 4 + 1] = wv.y;
            w[j * 4 + 2] = wv.z; w[j * 4 + 3] = wv.w;
        }

        float accs[4];
        #pragma unroll
        for (int t = 0; t < 4; t++) {
            const float4* xrow =
                (const float4*)(x + (((b * 4 + t) * 256 + s) << 9));
            float a = 0.0f;
            #pragma unroll
            for (int j = 0; j < 4; j++) {
                const float4 xv = xrow[lane + j * 32];
                a = fmaf(xv.x, w[j * 4 + 0], a);
                a = fmaf(xv.y, w[j * 4 + 1], a);
                a = fmaf(xv.z, w[j * 4 + 2], a);
                a = fmaf(xv.w, w[j * 4 + 3], a);
            }
            #pragma unroll
            for (int o = 16; o; o >>= 1)
                a += __shfl_xor_sync(0xFFFFFFFFu, a, o);
            accs[t] = a;
        }

        // ambiguity test (warp-uniform)
        bool amb = false;
        {
            float v = 0.0f;
            #pragma unroll
            for (int t = 0; t < 4; t++) {
                v = fmaf(beta, v, accs[t]);
                amb |= (fabsf(v - 1.0f) < AMB_EPS);
                v = (v > 1.0f) ? 0.0f : v;
            }
        }

        if (lane == 0) {
            if (amb) {
                const unsigned int pos = atomicAdd(&g_amb_count, 1u);
                if (pos < AMB_CAP) g_amb[pos] = idx;
            } else {
                float v = 0.0f;
                #pragma unroll
                for (int t = 0; t < 4; t++) {
                    v = fmaf(beta, v, accs[t]);
                    const bool fire = (v > 1.0f);
                    const __half old = g_spk[bse + (size_t)t * ts];
                    const bool oldf = (__half2float(old) > 0.5f);
                    if (fire != oldf) {
                        g_spk[bse + (size_t)t * ts] = fire ? one : zero;
                        delta += fire ? 1 : -1;
                    }
                    v = fire ? 0.0f : v;
                }
            }
        }
    }

    #pragma unroll
    for (int o = 16; o; o >>= 1) delta += __shfl_down_sync(0xFFFFFFFFu, delta, o);
    __shared__ int wsum[8];
    if (lane == 0) wsum[threadIdx.x >> 5] = delta;
    __syncthreads();
    if (threadIdx.x == 0) {
        int tot = 0;
        #pragma unroll
        for (int w = 0; w < 8; w++) tot += wsum[w];
        if (tot != 0) atomicAdd(&g_fix_delta, tot);
    }
}

// ============================================================================
// fixup_b: exact sequential fp32 resolve for ambiguous neurons (rare).
// Warp-cooperative smem staging, lane 0 runs the reference fma order.
// ============================================================================
__global__ __launch_bounds__(256) void fixup_b(
    const float* __restrict__ x, const float* __restrict__ w1)
{
    __shared__ float s_w[8][512];
    __shared__ float s_x[8][512];

    const unsigned int n = min(g_amb_count, (unsigned int)AMB_CAP);
    const int lane = threadIdx.x & 31;
    const int wib  = threadIdx.x >> 5;
    const unsigned int warp = (blockIdx.x * 256 + threadIdx.x) >> 5;
    const unsigned int nwarps = (gridDim.x * 256) >> 5;
    int delta = 0;

    const float beta = (float)(1.0 - 1.0 / 20.0);
    const __half one  = __float2half(1.0f);
    const __half zero = __float2half(0.0f);

    for (unsigned int i = warp; i < n; i += nwarps) {
        const unsigned int idx = g_amb[i];
        const int    hid = (int)(idx & 2047u);
        const size_t bs  = idx >> 11;
        const size_t b   = bs >> 8;
        const size_t s   = bs & 255;
        const size_t bse = ((b * 4) * 256 + s) * 2048 + hid;
        const size_t ts  = 256UL * 2048UL;

        const float4* wrow = (const float4*)(w1 + (size_t)hid * 512);
        #pragma unroll
        for (int j = 0; j < 4; j++)
            *(float4*)&s_w[wib][(lane + j * 32) * 4] = wrow[lane + j * 32];

        float accs[4];
        #pragma unroll
        for (int t = 0; t < 4; t++) {
            const float4* xrow =
                (const float4*)(x + (((b * 4 + t) * 256 + s) << 9));
            #pragma unroll
            for (int j = 0; j < 4; j++)
                *(float4*)&s_x[wib][(lane + j * 32) * 4] = xrow[lane + j * 32];
            __syncwarp();
            if (lane == 0) {
                float a = 0.0f;
                #pragma unroll 8
                for (int k = 0; k < 512; k++)
                    a = fmaf(s_x[wib][k], s_w[wib][k], a);
                accs[t] = a;
            }
            __syncwarp();
        }

        if (lane == 0) {
            float v = 0.0f;
            #pragma unroll
            for (int t = 0; t < 4; t++) {
                v = fmaf(beta, v, accs[t]);
                const bool fire = (v > 1.0f);
                const __half old = g_spk[bse + (size_t)t * ts];
                const bool oldf = (__half2float(old) > 0.5f);
                if (fire != oldf) {
                    g_spk[bse + (size_t)t * ts] = fire ? one : zero;
                    delta += fire ? 1 : -1;
                }
                v = fire ? 0.0f : v;
            }
        }
    }

    #pragma unroll
    for (int o = 16; o; o >>= 1) delta += __shfl_down_sync(0xFFFFFFFFu, delta, o);
    __shared__ int wsum[8];
    if (lane == 0) wsum[wib] = delta;
    __syncthreads();
    if (threadIdx.x == 0) {
        int tot = 0;
        #pragma unroll
        for (int w = 0; w < 8; w++) tot += wsum[w];
        if (tot != 0) atomicAdd(&g_fix_delta, tot);
    }
}

__global__ __launch_bounds__(1024) void rate_kernel(float* __restrict__ out_rate)
{
    long long s = 0;
    for (int i = threadIdx.x; i < 2048; i += 1024) s += g_partial[i];
    #pragma unroll
    for (int o = 16; o; o >>= 1) s += __shfl_down_sync(0xFFFFFFFFu, s, o);
    __shared__ long long sh[32];
    if ((threadIdx.x & 31) == 0) sh[threadIdx.x >> 5] = s;
    __syncthreads();
    if (threadIdx.x == 0) {
        long long tot = 0;
        #pragma unroll
        for (int w = 0; w < 32; w++) tot += sh[w];
        tot += g_fix_delta;
        *out_rate = (float)((double)tot / 33554432.0);
    }
}

// ============================================================================
extern "C" void kernel_launch(void* const* d_in, const int* in_sizes, int n_in,
                              void* d_out, int out_size)
{
    const float* x  = (const float*)d_in[0];
    const float* w1 = (const float*)d_in[1];
    const float* w2 = (const float*)d_in[2];
    float* out = (float*)d_out;

    __half *xh, *w1h, *w2h, *spk;
    cudaGetSymbolAddress((void**)&xh,  g_xh);
    cudaGetSymbolAddress((void**)&w1h, g_w1h);
    cudaGetSymbolAddress((void**)&w2h, g_w2h);
    cudaGetSymbolAddress((void**)&spk, g_spk);

    cudaFuncSetAttribute(gemm1_lif, cudaFuncAttributeMaxDynamicSharedMemorySize,
                         SMEM_ALLOC);
    cudaFuncSetAttribute(gemm_f16, cudaFuncAttributeMaxDynamicSharedMemorySize,
                         SMEM_ALLOC);

    cvt_x<<<8192, 256>>>(x, xh);
    cvt_w<<<2048, 256>>>(w1, w1h, w2, w2h);

    // GEMM1 + LIF fused (provisional spikes + flag list)
    gemm1_lif<<<dim3(16, 128), 256, SMEM_ALLOC>>>(xh, w1h);

    // phase A (high occupancy), phase B (rare exact resolves), rate
    fixup_a<<<1184, 256>>>(x, w1);
    fixup_b<<<256, 256>>>(x, w1);
    rate_kernel<<<1, 1024>>>(out + (out_size - 1));

    // GEMM2 on corrected spikes
    gemm_f16<<<dim3(512 / BN, 16384 / BM), 256, SMEM_ALLOC>>>(
        spk, w2h, out, 512, 2048 / BK, 2048, 2048);
}

// round 16
// speedup vs baseline: 1.2088x; 1.0433x over previous
#include <cuda_runtime.h>
#include <cuda_fp16.h>
#include <cstdint>

// ============================================================================
// SpikeMLP R16 = R14 + (a) high-throughput converts (8 floats/thread, uint4
// stores), (b) GEMM2 at 3 stages + 2 CTAs/SM. Fixup split unchanged.
// ============================================================================

#define STAGES 4
#define BM 128
#define BN 128
#define BK 64
#define STAGE_BYTES (BM * BK * 2)               // 16 KB
#define SMEM_B_OFF  (STAGES * STAGE_BYTES)      // 64 KB
#define SMEM_ALLOC  (2 * STAGES * STAGE_BYTES + 256)
#define HS_STRIDE 136                            // padded f32 row stride

// GEMM2 pipeline (3 stages, 2 CTAs/SM)
#define G2S 3
#define G2_SMEM_B_OFF (G2S * STAGE_BYTES)       // 48 KB
#define G2_SMEM_ALLOC (2 * G2S * STAGE_BYTES + 256)

#define FLAG_EPS 4e-3f
#define AMB_EPS  1e-4f
#define FLAG_CAP (1u << 22)
#define AMB_CAP  (1u << 20)

// ---------------- device scratch (no allocation allowed) -------------------
__device__ __align__(256) __half g_xh[16384UL * 512UL];        // 16 MB
__device__ __align__(256) __half g_w1h[2048UL * 512UL];        //  2 MB
__device__ __align__(256) __half g_w2h[512UL * 2048UL];        //  2 MB
__device__ __align__(256) __half g_spk[16384UL * 2048UL];      // 64 MB
__device__ unsigned int g_partial[2048];
__device__ unsigned int g_flags[FLAG_CAP];                      // 16 MB
__device__ unsigned int g_flag_count;
__device__ unsigned int g_amb[AMB_CAP];                         //  4 MB
__device__ unsigned int g_amb_count;
__device__ int          g_fix_delta;

// ---------------- PTX helpers ----------------------------------------------
__device__ __forceinline__ uint32_t smem_u32(const void* p) {
    uint32_t a;
    asm("{ .reg .u64 t; cvta.to.shared.u64 t, %1; cvt.u32.u64 %0, t; }"
        : "=r"(a) : "l"(p));
    return a;
}
__device__ __forceinline__ void cp16(uint32_t dst, const void* src) {
    asm volatile("cp.async.cg.shared.global [%0], [%1], 16;\n"
                 :: "r"(dst), "l"(src));
}
__device__ __forceinline__ void ldsm_x4(uint32_t r[4], uint32_t addr) {
    asm volatile("ldmatrix.sync.aligned.m8n8.x4.shared.b16 {%0,%1,%2,%3}, [%4];\n"
                 : "=r"(r[0]), "=r"(r[1]), "=r"(r[2]), "=r"(r[3]) : "r"(addr));
}
__device__ __forceinline__ void mma16816(float c[4], const uint32_t a[4],
                                         const uint32_t* b) {
    asm volatile(
        "mma.sync.aligned.m16n8k16.row.col.f32.f16.f16.f32 "
        "{%0,%1,%2,%3}, {%4,%5,%6,%7}, {%8,%9}, {%0,%1,%2,%3};\n"
        : "+f"(c[0]), "+f"(c[1]), "+f"(c[2]), "+f"(c[3])
        : "r"(a[0]), "r"(a[1]), "r"(a[2]), "r"(a[3]), "r"(b[0]), "r"(b[1]));
}

// ============================================================================
// GEMM1 fused with LIF (tile rows = 4 timesteps x 32 seq of one batch)
// ============================================================================
__global__ __launch_bounds__(256, 1) void gemm1_lif(
    const __half* __restrict__ A, const __half* __restrict__ B)
{
    extern __shared__ uint8_t dynsmem[];
    const uint32_t base = (smem_u32(dynsmem) + 127u) & ~127u;

    const int tid  = threadIdx.x;
    const int wid  = tid >> 5;
    const int lane = tid & 31;
    const int b    = blockIdx.y >> 3;
    const int s0   = (blockIdx.y & 7) * 32;
    const int n0   = blockIdx.x * BN;
    const int warp_m = (wid >> 2) * 64;
    const int warp_n = (wid & 3) * 32;

    int a_rb[4], a_xr[4];
    #pragma unroll
    for (int mt = 0; mt < 4; mt++) {
        const int r = warp_m + mt * 16 + (lane & 15);
        a_rb[mt] = r * 128;
        a_xr[mt] = (r & 7) << 4;
    }
    const int a_c0 = (lane >> 4) * 16;
    int b_rb[2], b_xr[2];
    {
        const int rl = (lane & 7) + ((lane >> 4) << 3);
        #pragma unroll
        for (int p = 0; p < 2; p++) {
            const int r = warp_n + p * 16 + rl;
            b_rb[p] = r * 128;
            b_xr[p] = (r & 7) << 4;
        }
    }
    const int b_c0 = ((lane >> 3) & 1) * 16;

    auto load_chunk = [&](int chunk, int slot) {
        const int k0 = chunk * BK;
        const uint32_t sA = base + slot * STAGE_BYTES;
        const uint32_t sB = base + SMEM_B_OFF + slot * STAGE_BYTES;
        #pragma unroll
        for (int r = 0; r < 4; r++) {
            const int idx = tid + r * 256;
            const int row = idx >> 3;
            const int cb  = (idx & 7) * 16;
            const int ga = b * 1024 + (row >> 5) * 256 + s0 + (row & 31);
            cp16(sA + row * 128 + (cb ^ ((row & 7) << 4)),
                 A + (size_t)ga * 512 + k0 + (cb >> 1));
            cp16(sB + row * 128 + (cb ^ ((row & 7) << 4)),
                 B + (size_t)(n0 + row) * 512 + k0 + (cb >> 1));
        }
    };

    float acc[4][4][4];
    #pragma unroll
    for (int mt = 0; mt < 4; mt++)
        #pragma unroll
        for (int nt = 0; nt < 4; nt++)
            #pragma unroll
            for (int q = 0; q < 4; q++) acc[mt][nt][q] = 0.0f;

    #pragma unroll
    for (int j = 0; j < STAGES - 1; j++) {
        load_chunk(j, j);
        asm volatile("cp.async.commit_group;\n" ::: "memory");
    }

    const int nchunks = 512 / BK;   // 8
    for (int i = 0; i < nchunks; i++) {
        asm volatile("cp.async.wait_group %0;\n" :: "n"(STAGES - 2));
        __syncthreads();
        const int lc = i + STAGES - 1;
        if (lc < nchunks) load_chunk(lc, lc & (STAGES - 1));
        asm volatile("cp.async.commit_group;\n" ::: "memory");

        const uint32_t sA = base + (i & (STAGES - 1)) * STAGE_BYTES;
        const uint32_t sB = base + SMEM_B_OFF + (i & (STAGES - 1)) * STAGE_BYTES;

        uint32_t af[2][4][4], bf[2][2][4];
        #pragma unroll
        for (int mt = 0; mt < 4; mt++)
            ldsm_x4(af[0][mt], sA + a_rb[mt] + ((a_c0) ^ a_xr[mt]));
        #pragma unroll
        for (int p = 0; p < 2; p++)
            ldsm_x4(bf[0][p], sB + b_rb[p] + ((b_c0) ^ b_xr[p]));

        #pragma unroll
        for (int ks = 0; ks < 4; ks++) {
            const int cur = ks & 1, nxt = cur ^ 1;
            if (ks < 3) {
                const int c = (ks + 1) * 32;
                #pragma unroll
                for (int mt = 0; mt < 4; mt++)
                    ldsm_x4(af[nxt][mt], sA + a_rb[mt] + ((c + a_c0) ^ a_xr[mt]));
                #pragma unroll
                for (int p = 0; p < 2; p++)
                    ldsm_x4(bf[nxt][p], sB + b_rb[p] + ((c + b_c0) ^ b_xr[p]));
            }
            #pragma unroll
            for (int mt = 0; mt < 4; mt++)
                #pragma unroll
                for (int nt = 0; nt < 4; nt++)
                    mma16816(acc[mt][nt], af[cur][mt],
                             &bf[cur][nt >> 1][(nt & 1) * 2]);
        }
    }

    // ---- epilogue: acc -> smem f32 tile, in-block LIF scan -----------------
    __syncthreads();
    float* hs = (float*)(dynsmem + ((128 - ((uintptr_t)dynsmem & 127)) & 127));
    #pragma unroll
    for (int mt = 0; mt < 4; mt++) {
        const int row = warp_m + mt * 16 + (lane >> 2);
        #pragma unroll
        for (int nt = 0; nt < 4; nt++) {
            const int col = warp_n + nt * 8 + (lane & 3) * 2;
            *(float2*)&hs[(size_t)row * HS_STRIDE + col] =
                make_float2(acc[mt][nt][0], acc[mt][nt][1]);
            *(float2*)&hs[(size_t)(row + 8) * HS_STRIDE + col] =
                make_float2(acc[mt][nt][2], acc[mt][nt][3]);
        }
    }
    __syncthreads();

    const float beta = (float)(1.0 - 1.0 / 20.0);
    const __half one  = __float2half(1.0f);
    const __half zero = __float2half(0.0f);
    int cnt = 0;

    #pragma unroll
    for (int iter = 0; iter < 16; iter++) {
        const int s   = (iter << 1) | (tid >> 7);
        const int col = tid & 127;
        float v = 0.0f;
        bool flagged = false;
        #pragma unroll
        for (int t = 0; t < 4; t++) {
            const float h = hs[(size_t)(t * 32 + s) * HS_STRIDE + col];
            v = fmaf(beta, v, h);
            flagged |= (fabsf(v - 1.0f) < FLAG_EPS);
            const bool fire = (v > 1.0f);
            g_spk[((size_t)(b * 4 + t) * 256 + s0 + s) * 2048 + n0 + col] =
                fire ? one : zero;
            cnt += fire ? 1 : 0;
            v = fire ? 0.0f : v;
        }
        const unsigned int mask = __ballot_sync(0xFFFFFFFFu, flagged);
        if (flagged) {
            const int leader = __ffs(mask) - 1;
            const int rank   = __popc(mask & ((1u << lane) - 1));
            unsigned int pos = 0;
            if (lane == leader) pos = atomicAdd(&g_flag_count, __popc(mask));
            pos = __shfl_sync(mask, pos, leader);
            const unsigned int nidx =
                (unsigned int)(((b * 256 + s0 + s) << 11) + n0 + col);
            if (pos + rank < FLAG_CAP) g_flags[pos + rank] = nidx;
        }
    }

    #pragma unroll
    for (int o = 16; o; o >>= 1) cnt += __shfl_down_sync(0xFFFFFFFFu, cnt, o);
    __shared__ int warpsum[8];
    if (lane == 0) warpsum[wid] = cnt;
    __syncthreads();
    if (tid == 0) {
        int tot = 0;
        #pragma unroll
        for (int w = 0; w < 8; w++) tot += warpsum[w];
        g_partial[blockIdx.y * 16 + blockIdx.x] = (unsigned int)tot;
    }
}

// ============================================================================
// fp16 NT GEMM (GEMM2): 3-stage pipeline, 2 CTAs/SM
// ============================================================================
__global__ __launch_bounds__(256, 2) void gemm_f16(
    const __half* __restrict__ A, const __half* __restrict__ B,
    float* __restrict__ C, int ldc, int nchunks, int a_rs, int b_rs)
{
    extern __shared__ uint8_t dynsmem[];
    const uint32_t base = (smem_u32(dynsmem) + 127u) & ~127u;

    const int tid  = threadIdx.x;
    const int wid  = tid >> 5;
    const int lane = tid & 31;
    const int m0   = blockIdx.y * BM;
    const int n0   = blockIdx.x * BN;
    const int warp_m = (wid >> 2) * 64;
    const int warp_n = (wid & 3) * 32;

    int a_rb[4], a_xr[4];
    #pragma unroll
    for (int mt = 0; mt < 4; mt++) {
        const int r = warp_m + mt * 16 + (lane & 15);
        a_rb[mt] = r * 128;
        a_xr[mt] = (r & 7) << 4;
    }
    const int a_c0 = (lane >> 4) * 16;
    int b_rb[2], b_xr[2];
    {
        const int rl = (lane & 7) + ((lane >> 4) << 3);
        #pragma unroll
        for (int p = 0; p < 2; p++) {
            const int r = warp_n + p * 16 + rl;
            b_rb[p] = r * 128;
            b_xr[p] = (r & 7) << 4;
        }
    }
    const int b_c0 = ((lane >> 3) & 1) * 16;

    auto load_chunk = [&](int chunk, int slot) {
        const int k0 = chunk * BK;
        const uint32_t sA = base + slot * STAGE_BYTES;
        const uint32_t sB = base + G2_SMEM_B_OFF + slot * STAGE_BYTES;
        #pragma unroll
        for (int r = 0; r < 4; r++) {
            const int idx = tid + r * 256;
            const int row = idx >> 3;
            const int cb  = (idx & 7) * 16;
            cp16(sA + row * 128 + (cb ^ ((row & 7) << 4)),
                 A + (size_t)(m0 + row) * a_rs + k0 + (cb >> 1));
            cp16(sB + row * 128 + (cb ^ ((row & 7) << 4)),
                 B + (size_t)(n0 + row) * b_rs + k0 + (cb >> 1));
        }
    };

    float acc[4][4][4];
    #pragma unroll
    for (int mt = 0; mt < 4; mt++)
        #pragma unroll
        for (int nt = 0; nt < 4; nt++)
            #pragma unroll
            for (int q = 0; q < 4; q++) acc[mt][nt][q] = 0.0f;

    #pragma unroll
    for (int j = 0; j < G2S - 1; j++) {
        load_chunk(j, j);
        asm volatile("cp.async.commit_group;\n" ::: "memory");
    }

    int slot = 0, lslot = G2S - 1;
    for (int i = 0; i < nchunks; i++) {
        asm volatile("cp.async.wait_group %0;\n" :: "n"(G2S - 2));
        __syncthreads();
        const int lc = i + G2S - 1;
        if (lc < nchunks) {
            load_chunk(lc, lslot);
            if (++lslot == G2S) lslot = 0;
        }
        asm volatile("cp.async.commit_group;\n" ::: "memory");

        const uint32_t sA = base + slot * STAGE_BYTES;
        const uint32_t sB = base + G2_SMEM_B_OFF + slot * STAGE_BYTES;
        if (++slot == G2S) slot = 0;

        uint32_t af[2][4][4], bf[2][2][4];
        #pragma unroll
        for (int mt = 0; mt < 4; mt++)
            ldsm_x4(af[0][mt], sA + a_rb[mt] + ((a_c0) ^ a_xr[mt]));
        #pragma unroll
        for (int p = 0; p < 2; p++)
            ldsm_x4(bf[0][p], sB + b_rb[p] + ((b_c0) ^ b_xr[p]));

        #pragma unroll
        for (int ks = 0; ks < 4; ks++) {
            const int cur = ks & 1, nxt = cur ^ 1;
            if (ks < 3) {
                const int c = (ks + 1) * 32;
                #pragma unroll
                for (int mt = 0; mt < 4; mt++)
                    ldsm_x4(af[nxt][mt], sA + a_rb[mt] + ((c + a_c0) ^ a_xr[mt]));
                #pragma unroll
                for (int p = 0; p < 2; p++)
                    ldsm_x4(bf[nxt][p], sB + b_rb[p] + ((c + b_c0) ^ b_xr[p]));
            }
            #pragma unroll
            for (int mt = 0; mt < 4; mt++)
                #pragma unroll
                for (int nt = 0; nt < 4; nt++)
                    mma16816(acc[mt][nt], af[cur][mt],
                             &bf[cur][nt >> 1][(nt & 1) * 2]);
        }
    }

    #pragma unroll
    for (int mt = 0; mt < 4; mt++) {
        #pragma unroll
        for (int nt = 0; nt < 4; nt++) {
            const int row = m0 + warp_m + mt * 16 + (lane >> 2);
            const int col = n0 + warp_n + nt * 8 + (lane & 3) * 2;
            float* c0 = C + (size_t)row * ldc + col;
            float* c1 = C + (size_t)(row + 8) * ldc + col;
            *(float2*)c0 = make_float2(acc[mt][nt][0], acc[mt][nt][1]);
            *(float2*)c1 = make_float2(acc[mt][nt][2], acc[mt][nt][3]);
        }
    }
}

// ============================================================================
// High-throughput converts: 8 floats/thread, single uint4 (16B) store.
// ============================================================================
__device__ __forceinline__ void cvt8_store(const float* __restrict__ src,
                                           __half* __restrict__ dst,
                                           size_t i)
{
    const float4 v0 = *(const float4*)(src + i);
    const float4 v1 = *(const float4*)(src + i + 4);
    __half2 h0 = __floats2half2_rn(v0.x, v0.y);
    __half2 h1 = __floats2half2_rn(v0.z, v0.w);
    __half2 h2 = __floats2half2_rn(v1.x, v1.y);
    __half2 h3 = __floats2half2_rn(v1.z, v1.w);
    uint4 o;
    o.x = *(uint32_t*)&h0;
    o.y = *(uint32_t*)&h1;
    o.z = *(uint32_t*)&h2;
    o.w = *(uint32_t*)&h3;
    *(uint4*)(dst + i) = o;
}

__global__ __launch_bounds__(256) void cvt_x(const float* __restrict__ src,
                                             __half* __restrict__ dst)
{
    if (blockIdx.x == 0 && threadIdx.x == 0) {
        g_flag_count = 0;
        g_amb_count = 0;
        g_fix_delta = 0;
    }
    const size_t i = ((size_t)blockIdx.x * 256 + threadIdx.x) * 8;
    cvt8_store(src, dst, i);
}

__global__ __launch_bounds__(256) void cvt_w(
    const float* __restrict__ w1, __half* __restrict__ w1d,
    const float* __restrict__ w2, __half* __restrict__ w2d)
{
    const int half_grid = (int)gridDim.x >> 1;
    const bool second = blockIdx.x >= half_grid;
    const float* src = second ? w2 : w1;
    __half* dst = second ? w2d : w1d;
    const size_t i =
        ((size_t)(blockIdx.x - (second ? half_grid : 0)) * 256 + threadIdx.x) * 8;
    cvt8_store(src, dst, i);
}

// ============================================================================
// fixup_a: phase A only (butterfly dots, w in regs), 4 CTAs/SM; ambiguous
// neurons deferred to g_amb, confident decisions applied directly.
// ============================================================================
__global__ __launch_bounds__(256, 4) void fixup_a(
    const float* __restrict__ x, const float* __restrict__ w1)
{
    const unsigned int n = min(g_flag_count, (unsigned int)FLAG_CAP);
    const int lane = threadIdx.x & 31;
    const unsigned int warp = (blockIdx.x * 256 + threadIdx.x) >> 5;
    const unsigned int nwarps = (gridDim.x * 256) >> 5;
    int delta = 0;

    const float beta = (float)(1.0 - 1.0 / 20.0);
    const __half one  = __float2half(1.0f);
    const __half zero = __float2half(0.0f);

    for (unsigned int i = warp; i < n; i += nwarps) {
        const unsigned int idx = g_flags[i];
        const int    hid = (int)(idx & 2047u);
        const size_t bs  = idx >> 11;
        const size_t b   = bs >> 8;
        const size_t s   = bs & 255;
        const size_t bse = ((b * 4) * 256 + s) * 2048 + hid;
        const size_t ts  = 256UL * 2048UL;

        const float4* wrow = (const float4*)(w1 + (size_t)hid * 512);
        float w[16];
        #pragma unroll
        for (int j = 0; j < 4; j++) {
            const float4 wv = wrow[lane + j * 32];
            w[j * 4 + 0] = wv.x; w[j * 4 + 1] = wv.y;
            w[j * 4 + 2] = wv.z; w[j * 4 + 3] = wv.w;
        }

        float accs[4];
        #pragma unroll
        for (int t = 0; t < 4; t++) {
            const float4* xrow =
                (const float4*)(x + (((b * 4 + t) * 256 + s) << 9));
            float a = 0.0f;
            #pragma unroll
            for (int j = 0; j < 4; j++) {
                const float4 xv = xrow[lane + j * 32];
                a = fmaf(xv.x, w[j * 4 + 0], a);
                a = fmaf(xv.y, w[j * 4 + 1], a);
                a = fmaf(xv.z, w[j * 4 + 2], a);
                a = fmaf(xv.w, w[j * 4 + 3], a);
            }
            #pragma unroll
            for (int o = 16; o; o >>= 1)
                a += __shfl_xor_sync(0xFFFFFFFFu, a, o);
            accs[t] = a;
        }

        bool amb = false;
        {
            float v = 0.0f;
            #pragma unroll
            for (int t = 0; t < 4; t++) {
                v = fmaf(beta, v, accs[t]);
                amb |= (fabsf(v - 1.0f) < AMB_EPS);
                v = (v > 1.0f) ? 0.0f : v;
            }
        }

        if (lane == 0) {
            if (amb) {
                const unsigned int pos = atomicAdd(&g_amb_count, 1u);
                if (pos < AMB_CAP) g_amb[pos] = idx;
            } else {
                float v = 0.0f;
                #pragma unroll
                for (int t = 0; t < 4; t++) {
                    v = fmaf(beta, v, accs[t]);
                    const bool fire = (v > 1.0f);
                    const __half old = g_spk[bse + (size_t)t * ts];
                    const bool oldf = (__half2float(old) > 0.5f);
                    if (fire != oldf) {
                        g_spk[bse + (size_t)t * ts] = fire ? one : zero;
                        delta += fire ? 1 : -1;
                    }
                    v = fire ? 0.0f : v;
                }
            }
        }
    }

    #pragma unroll
    for (int o = 16; o; o >>= 1) delta += __shfl_down_sync(0xFFFFFFFFu, delta, o);
    __shared__ int wsum[8];
    if (lane == 0) wsum[threadIdx.x >> 5] = delta;
    __syncthreads();
    if (threadIdx.x == 0) {
        int tot = 0;
        #pragma unroll
        for (int w = 0; w < 8; w++) tot += wsum[w];
        if (tot != 0) atomicAdd(&g_fix_delta, tot);
    }
}

// ============================================================================
// fixup_b: exact sequential fp32 resolve for ambiguous neurons (rare).
// ============================================================================
__global__ __launch_bounds__(256) void fixup_b(
    const float* __restrict__ x, const float* __restrict__ w1)
{
    __shared__ float s_w[8][512];
    __shared__ float s_x[8][512];

    const unsigned int n = min(g_amb_count, (unsigned int)AMB_CAP);
    const int lane = threadIdx.x & 31;
    const int wib  = threadIdx.x >> 5;
    const unsigned int warp = (blockIdx.x * 256 + threadIdx.x) >> 5;
    const unsigned int nwarps = (gridDim.x * 256) >> 5;
    int delta = 0;

    const float beta = (float)(1.0 - 1.0 / 20.0);
    const __half one  = __float2half(1.0f);
    const __half zero = __float2half(0.0f);

    for (unsigned int i = warp; i < n; i += nwarps) {
        const unsigned int idx = g_amb[i];
        const int    hid = (int)(idx & 2047u);
        const size_t bs  = idx >> 11;
        const size_t b   = bs >> 8;
        const size_t s   = bs & 255;
        const size_t bse = ((b * 4) * 256 + s) * 2048 + hid;
        const size_t ts  = 256UL * 2048UL;

        const float4* wrow = (const float4*)(w1 + (size_t)hid * 512);
        #pragma unroll
        for (int j = 0; j < 4; j++)
            *(float4*)&s_w[wib][(lane + j * 32) * 4] = wrow[lane + j * 32];

        float accs[4];
        #pragma unroll
        for (int t = 0; t < 4; t++) {
            const float4* xrow =
                (const float4*)(x + (((b * 4 + t) * 256 + s) << 9));
            #pragma unroll
            for (int j = 0; j < 4; j++)
                *(float4*)&s_x[wib][(lane + j * 32) * 4] = xrow[lane + j * 32];
            __syncwarp();
            if (lane == 0) {
                float a = 0.0f;
                #pragma unroll 8
                for (int k = 0; k < 512; k++)
                    a = fmaf(s_x[wib][k], s_w[wib][k], a);
                accs[t] = a;
            }
            __syncwarp();
        }

        if (lane == 0) {
            float v = 0.0f;
            #pragma unroll
            for (int t = 0; t < 4; t++) {
                v = fmaf(beta, v, accs[t]);
                const bool fire = (v > 1.0f);
                const __half old = g_spk[bse + (size_t)t * ts];
                const bool oldf = (__half2float(old) > 0.5f);
                if (fire != oldf) {
                    g_spk[bse + (size_t)t * ts] = fire ? one : zero;
                    delta += fire ? 1 : -1;
                }
                v = fire ? 0.0f : v;
            }
        }
    }

    #pragma unroll
    for (int o = 16; o; o >>= 1) delta += __shfl_down_sync(0xFFFFFFFFu, delta, o);
    __shared__ int wsum[8];
    if (lane == 0) wsum[wib] = delta;
    __syncthreads();
    if (threadIdx.x == 0) {
        int tot = 0;
        #pragma unroll
        for (int w = 0; w < 8; w++) tot += wsum[w];
        if (tot != 0) atomicAdd(&g_fix_delta, tot);
    }
}

__global__ __launch_bounds__(1024) void rate_kernel(float* __restrict__ out_rate)
{
    long long s = 0;
    for (int i = threadIdx.x; i < 2048; i += 1024) s += g_partial[i];
    #pragma unroll
    for (int o = 16; o; o >>= 1) s += __shfl_down_sync(0xFFFFFFFFu, s, o);
    __shared__ long long sh[32];
    if ((threadIdx.x & 31) == 0) sh[threadIdx.x >> 5] = s;
    __syncthreads();
    if (threadIdx.x == 0) {
        long long tot = 0;
        #pragma unroll
        for (int w = 0; w < 32; w++) tot += sh[w];
        tot += g_fix_delta;
        *out_rate = (float)((double)tot / 33554432.0);
    }
}

// ============================================================================
extern "C" void kernel_launch(void* const* d_in, const int* in_sizes, int n_in,
                              void* d_out, int out_size)
{
    const float* x  = (const float*)d_in[0];
    const float* w1 = (const float*)d_in[1];
    const float* w2 = (const float*)d_in[2];
    float* out = (float*)d_out;

    __half *xh, *w1h, *w2h, *spk;
    cudaGetSymbolAddress((void**)&xh,  g_xh);
    cudaGetSymbolAddress((void**)&w1h, g_w1h);
    cudaGetSymbolAddress((void**)&w2h, g_w2h);
    cudaGetSymbolAddress((void**)&spk, g_spk);

    cudaFuncSetAttribute(gemm1_lif, cudaFuncAttributeMaxDynamicSharedMemorySize,
                         SMEM_ALLOC);
    cudaFuncSetAttribute(gemm_f16, cudaFuncAttributeMaxDynamicSharedMemorySize,
                         G2_SMEM_ALLOC);

    // converts: 8 floats/thread (x: 8.4M elems -> 4096 blocks; w: 2x1M -> 1024)
    cvt_x<<<4096, 256>>>(x, xh);
    cvt_w<<<1024, 256>>>(w1, w1h, w2, w2h);

    // GEMM1 + LIF fused (provisional spikes + flag list)
    gemm1_lif<<<dim3(16, 128), 256, SMEM_ALLOC>>>(xh, w1h);

    // phase A (high occupancy), phase B (rare exact resolves), rate
    fixup_a<<<1184, 256>>>(x, w1);
    fixup_b<<<256, 256>>>(x, w1);
    rate_kernel<<<1, 1024>>>(out + (out_size - 1));

    // GEMM2 on corrected spikes (3-stage, 2 CTAs/SM)
    gemm_f16<<<dim3(512 / BN, 16384 / BM), 256, G2_SMEM_ALLOC>>>(
        spk, w2h, out, 512, 2048 / BK, 2048, 2048);
}

// round 17
// speedup vs baseline: 1.4007x; 1.1588x over previous
#include <cuda_runtime.h>
#include <cuda_fp16.h>
#include <cstdint>

// ============================================================================
// SpikeMLP R17 = R16 + gemm1_lif at 3-stage pipeline / 2 CTAs per SM
// (R8-vs-R9 differential showed the 3-stage 2-CTA GEMM pair was faster; R16
// banked the GEMM2 half, this banks the GEMM1 half). Everything else as R16.
// ============================================================================

#define BM 128
#define BN 128
#define BK 64
#define STAGE_BYTES (BM * BK * 2)               // 16 KB
#define HS_STRIDE 136                            // padded f32 row stride

// GEMM1 pipeline (3 stages, 2 CTAs/SM); 96KB smem also holds the 69.6KB LIF tile
#define G1S 3
#define G1_SMEM_B_OFF (G1S * STAGE_BYTES)       // 48 KB
#define G1_SMEM_ALLOC (2 * G1S * STAGE_BYTES + 256)

// GEMM2 pipeline (3 stages, 2 CTAs/SM)
#define G2S 3
#define G2_SMEM_B_OFF (G2S * STAGE_BYTES)       // 48 KB
#define G2_SMEM_ALLOC (2 * G2S * STAGE_BYTES + 256)

#define FLAG_EPS 4e-3f
#define AMB_EPS  1e-4f
#define FLAG_CAP (1u << 22)
#define AMB_CAP  (1u << 20)

// ---------------- device scratch (no allocation allowed) -------------------
__device__ __align__(256) __half g_xh[16384UL * 512UL];        // 16 MB
__device__ __align__(256) __half g_w1h[2048UL * 512UL];        //  2 MB
__device__ __align__(256) __half g_w2h[512UL * 2048UL];        //  2 MB
__device__ __align__(256) __half g_spk[16384UL * 2048UL];      // 64 MB
__device__ unsigned int g_partial[2048];
__device__ unsigned int g_flags[FLAG_CAP];                      // 16 MB
__device__ unsigned int g_flag_count;
__device__ unsigned int g_amb[AMB_CAP];                         //  4 MB
__device__ unsigned int g_amb_count;
__device__ int          g_fix_delta;

// ---------------- PTX helpers ----------------------------------------------
__device__ __forceinline__ uint32_t smem_u32(const void* p) {
    uint32_t a;
    asm("{ .reg .u64 t; cvta.to.shared.u64 t, %1; cvt.u32.u64 %0, t; }"
        : "=r"(a) : "l"(p));
    return a;
}
__device__ __forceinline__ void cp16(uint32_t dst, const void* src) {
    asm volatile("cp.async.cg.shared.global [%0], [%1], 16;\n"
                 :: "r"(dst), "l"(src));
}
__device__ __forceinline__ void ldsm_x4(uint32_t r[4], uint32_t addr) {
    asm volatile("ldmatrix.sync.aligned.m8n8.x4.shared.b16 {%0,%1,%2,%3}, [%4];\n"
                 : "=r"(r[0]), "=r"(r[1]), "=r"(r[2]), "=r"(r[3]) : "r"(addr));
}
__device__ __forceinline__ void mma16816(float c[4], const uint32_t a[4],
                                         const uint32_t* b) {
    asm volatile(
        "mma.sync.aligned.m16n8k16.row.col.f32.f16.f16.f32 "
        "{%0,%1,%2,%3}, {%4,%5,%6,%7}, {%8,%9}, {%0,%1,%2,%3};\n"
        : "+f"(c[0]), "+f"(c[1]), "+f"(c[2]), "+f"(c[3])
        : "r"(a[0]), "r"(a[1]), "r"(a[2]), "r"(a[3]), "r"(b[0]), "r"(b[1]));
}

// ============================================================================
// GEMM1 fused with LIF (tile rows = 4 timesteps x 32 seq of one batch)
// 3-stage cp.async pipeline, 2 CTAs/SM.
// ============================================================================
__global__ __launch_bounds__(256, 2) void gemm1_lif(
    const __half* __restrict__ A, const __half* __restrict__ B)
{
    extern __shared__ uint8_t dynsmem[];
    const uint32_t base = (smem_u32(dynsmem) + 127u) & ~127u;

    const int tid  = threadIdx.x;
    const int wid  = tid >> 5;
    const int lane = tid & 31;
    const int b    = blockIdx.y >> 3;
    const int s0   = (blockIdx.y & 7) * 32;
    const int n0   = blockIdx.x * BN;
    const int warp_m = (wid >> 2) * 64;
    const int warp_n = (wid & 3) * 32;

    int a_rb[4], a_xr[4];
    #pragma unroll
    for (int mt = 0; mt < 4; mt++) {
        const int r = warp_m + mt * 16 + (lane & 15);
        a_rb[mt] = r * 128;
        a_xr[mt] = (r & 7) << 4;
    }
    const int a_c0 = (lane >> 4) * 16;
    int b_rb[2], b_xr[2];
    {
        const int rl = (lane & 7) + ((lane >> 4) << 3);
        #pragma unroll
        for (int p = 0; p < 2; p++) {
            const int r = warp_n + p * 16 + rl;
            b_rb[p] = r * 128;
            b_xr[p] = (r & 7) << 4;
        }
    }
    const int b_c0 = ((lane >> 3) & 1) * 16;

    auto load_chunk = [&](int chunk, int slot) {
        const int k0 = chunk * BK;
        const uint32_t sA = base + slot * STAGE_BYTES;
        const uint32_t sB = base + G1_SMEM_B_OFF + slot * STAGE_BYTES;
        #pragma unroll
        for (int r = 0; r < 4; r++) {
            const int idx = tid + r * 256;
            const int row = idx >> 3;
            const int cb  = (idx & 7) * 16;
            const int ga = b * 1024 + (row >> 5) * 256 + s0 + (row & 31);
            cp16(sA + row * 128 + (cb ^ ((row & 7) << 4)),
                 A + (size_t)ga * 512 + k0 + (cb >> 1));
            cp16(sB + row * 128 + (cb ^ ((row & 7) << 4)),
                 B + (size_t)(n0 + row) * 512 + k0 + (cb >> 1));
        }
    };

    float acc[4][4][4];
    #pragma unroll
    for (int mt = 0; mt < 4; mt++)
        #pragma unroll
        for (int nt = 0; nt < 4; nt++)
            #pragma unroll
            for (int q = 0; q < 4; q++) acc[mt][nt][q] = 0.0f;

    #pragma unroll
    for (int j = 0; j < G1S - 1; j++) {
        load_chunk(j, j);
        asm volatile("cp.async.commit_group;\n" ::: "memory");
    }

    const int nchunks = 512 / BK;   // 8
    int slot = 0, lslot = G1S - 1;
    for (int i = 0; i < nchunks; i++) {
        asm volatile("cp.async.wait_group %0;\n" :: "n"(G1S - 2));
        __syncthreads();
        const int lc = i + G1S - 1;
        if (lc < nchunks) {
            load_chunk(lc, lslot);
            if (++lslot == G1S) lslot = 0;
        }
        asm volatile("cp.async.commit_group;\n" ::: "memory");

        const uint32_t sA = base + slot * STAGE_BYTES;
        const uint32_t sB = base + G1_SMEM_B_OFF + slot * STAGE_BYTES;
        if (++slot == G1S) slot = 0;

        uint32_t af[2][4][4], bf[2][2][4];
        #pragma unroll
        for (int mt = 0; mt < 4; mt++)
            ldsm_x4(af[0][mt], sA + a_rb[mt] + ((a_c0) ^ a_xr[mt]));
        #pragma unroll
        for (int p = 0; p < 2; p++)
            ldsm_x4(bf[0][p], sB + b_rb[p] + ((b_c0) ^ b_xr[p]));

        #pragma unroll
        for (int ks = 0; ks < 4; ks++) {
            const int cur = ks & 1, nxt = cur ^ 1;
            if (ks < 3) {
                const int c = (ks + 1) * 32;
                #pragma unroll
                for (int mt = 0; mt < 4; mt++)
                    ldsm_x4(af[nxt][mt], sA + a_rb[mt] + ((c + a_c0) ^ a_xr[mt]));
                #pragma unroll
                for (int p = 0; p < 2; p++)
                    ldsm_x4(bf[nxt][p], sB + b_rb[p] + ((c + b_c0) ^ b_xr[p]));
            }
            #pragma unroll
            for (int mt = 0; mt < 4; mt++)
                #pragma unroll
                for (int nt = 0; nt < 4; nt++)
                    mma16816(acc[mt][nt], af[cur][mt],
                             &bf[cur][nt >> 1][(nt & 1) * 2]);
        }
    }

    // ---- epilogue: acc -> smem f32 tile, in-block LIF scan -----------------
    __syncthreads();
    float* hs = (float*)(dynsmem + ((128 - ((uintptr_t)dynsmem & 127)) & 127));
    #pragma unroll
    for (int mt = 0; mt < 4; mt++) {
        const int row = warp_m + mt * 16 + (lane >> 2);
        #pragma unroll
        for (int nt = 0; nt < 4; nt++) {
            const int col = warp_n + nt * 8 + (lane & 3) * 2;
            *(float2*)&hs[(size_t)row * HS_STRIDE + col] =
                make_float2(acc[mt][nt][0], acc[mt][nt][1]);
            *(float2*)&hs[(size_t)(row + 8) * HS_STRIDE + col] =
                make_float2(acc[mt][nt][2], acc[mt][nt][3]);
        }
    }
    __syncthreads();

    const float beta = (float)(1.0 - 1.0 / 20.0);
    const __half one  = __float2half(1.0f);
    const __half zero = __float2half(0.0f);
    int cnt = 0;

    #pragma unroll
    for (int iter = 0; iter < 16; iter++) {
        const int s   = (iter << 1) | (tid >> 7);
        const int col = tid & 127;
        float v = 0.0f;
        bool flagged = false;
        #pragma unroll
        for (int t = 0; t < 4; t++) {
            const float h = hs[(size_t)(t * 32 + s) * HS_STRIDE + col];
            v = fmaf(beta, v, h);
            flagged |= (fabsf(v - 1.0f) < FLAG_EPS);
            const bool fire = (v > 1.0f);
            g_spk[((size_t)(b * 4 + t) * 256 + s0 + s) * 2048 + n0 + col] =
                fire ? one : zero;
            cnt += fire ? 1 : 0;
            v = fire ? 0.0f : v;
        }
        const unsigned int mask = __ballot_sync(0xFFFFFFFFu, flagged);
        if (flagged) {
            const int leader = __ffs(mask) - 1;
            const int rank   = __popc(mask & ((1u << lane) - 1));
            unsigned int pos = 0;
            if (lane == leader) pos = atomicAdd(&g_flag_count, __popc(mask));
            pos = __shfl_sync(mask, pos, leader);
            const unsigned int nidx =
                (unsigned int)(((b * 256 + s0 + s) << 11) + n0 + col);
            if (pos + rank < FLAG_CAP) g_flags[pos + rank] = nidx;
        }
    }

    #pragma unroll
    for (int o = 16; o; o >>= 1) cnt += __shfl_down_sync(0xFFFFFFFFu, cnt, o);
    __shared__ int warpsum[8];
    if (lane == 0) warpsum[wid] = cnt;
    __syncthreads();
    if (tid == 0) {
        int tot = 0;
        #pragma unroll
        for (int w = 0; w < 8; w++) tot += warpsum[w];
        g_partial[blockIdx.y * 16 + blockIdx.x] = (unsigned int)tot;
    }
}

// ============================================================================
// fp16 NT GEMM (GEMM2): 3-stage pipeline, 2 CTAs/SM
// ============================================================================
__global__ __launch_bounds__(256, 2) void gemm_f16(
    const __half* __restrict__ A, const __half* __restrict__ B,
    float* __restrict__ C, int ldc, int nchunks, int a_rs, int b_rs)
{
    extern __shared__ uint8_t dynsmem[];
    const uint32_t base = (smem_u32(dynsmem) + 127u) & ~127u;

    const int tid  = threadIdx.x;
    const int wid  = tid >> 5;
    const int lane = tid & 31;
    const int m0   = blockIdx.y * BM;
    const int n0   = blockIdx.x * BN;
    const int warp_m = (wid >> 2) * 64;
    const int warp_n = (wid & 3) * 32;

    int a_rb[4], a_xr[4];
    #pragma unroll
    for (int mt = 0; mt < 4; mt++) {
        const int r = warp_m + mt * 16 + (lane & 15);
        a_rb[mt] = r * 128;
        a_xr[mt] = (r & 7) << 4;
    }
    const int a_c0 = (lane >> 4) * 16;
    int b_rb[2], b_xr[2];
    {
        const int rl = (lane & 7) + ((lane >> 4) << 3);
        #pragma unroll
        for (int p = 0; p < 2; p++) {
            const int r = warp_n + p * 16 + rl;
            b_rb[p] = r * 128;
            b_xr[p] = (r & 7) << 4;
        }
    }
    const int b_c0 = ((lane >> 3) & 1) * 16;

    auto load_chunk = [&](int chunk, int slot) {
        const int k0 = chunk * BK;
        const uint32_t sA = base + slot * STAGE_BYTES;
        const uint32_t sB = base + G2_SMEM_B_OFF + slot * STAGE_BYTES;
        #pragma unroll
        for (int r = 0; r < 4; r++) {
            const int idx = tid + r * 256;
            const int row = idx >> 3;
            const int cb  = (idx & 7) * 16;
            cp16(sA + row * 128 + (cb ^ ((row & 7) << 4)),
                 A + (size_t)(m0 + row) * a_rs + k0 + (cb >> 1));
            cp16(sB + row * 128 + (cb ^ ((row & 7) << 4)),
                 B + (size_t)(n0 + row) * b_rs + k0 + (cb >> 1));
        }
    };

    float acc[4][4][4];
    #pragma unroll
    for (int mt = 0; mt < 4; mt++)
        #pragma unroll
        for (int nt = 0; nt < 4; nt++)
            #pragma unroll
            for (int q = 0; q < 4; q++) acc[mt][nt][q] = 0.0f;

    #pragma unroll
    for (int j = 0; j < G2S - 1; j++) {
        load_chunk(j, j);
        asm volatile("cp.async.commit_group;\n" ::: "memory");
    }

    int slot = 0, lslot = G2S - 1;
    for (int i = 0; i < nchunks; i++) {
        asm volatile("cp.async.wait_group %0;\n" :: "n"(G2S - 2));
        __syncthreads();
        const int lc = i + G2S - 1;
        if (lc < nchunks) {
            load_chunk(lc, lslot);
            if (++lslot == G2S) lslot = 0;
        }
        asm volatile("cp.async.commit_group;\n" ::: "memory");

        const uint32_t sA = base + slot * STAGE_BYTES;
        const uint32_t sB = base + G2_SMEM_B_OFF + slot * STAGE_BYTES;
        if (++slot == G2S) slot = 0;

        uint32_t af[2][4][4], bf[2][2][4];
        #pragma unroll
        for (int mt = 0; mt < 4; mt++)
            ldsm_x4(af[0][mt], sA + a_rb[mt] + ((a_c0) ^ a_xr[mt]));
        #pragma unroll
        for (int p = 0; p < 2; p++)
            ldsm_x4(bf[0][p], sB + b_rb[p] + ((b_c0) ^ b_xr[p]));

        #pragma unroll
        for (int ks = 0; ks < 4; ks++) {
            const int cur = ks & 1, nxt = cur ^ 1;
            if (ks < 3) {
                const int c = (ks + 1) * 32;
                #pragma unroll
                for (int mt = 0; mt < 4; mt++)
                    ldsm_x4(af[nxt][mt], sA + a_rb[mt] + ((c + a_c0) ^ a_xr[mt]));
                #pragma unroll
                for (int p = 0; p < 2; p++)
                    ldsm_x4(bf[nxt][p], sB + b_rb[p] + ((c + b_c0) ^ b_xr[p]));
            }
            #pragma unroll
            for (int mt = 0; mt < 4; mt++)
                #pragma unroll
                for (int nt = 0; nt < 4; nt++)
                    mma16816(acc[mt][nt], af[cur][mt],
                             &bf[cur][nt >> 1][(nt & 1) * 2]);
        }
    }

    #pragma unroll
    for (int mt = 0; mt < 4; mt++) {
        #pragma unroll
        for (int nt = 0; nt < 4; nt++) {
            const int row = m0 + warp_m + mt * 16 + (lane >> 2);
            const int col = n0 + warp_n + nt * 8 + (lane & 3) * 2;
            float* c0 = C + (size_t)row * ldc + col;
            float* c1 = C + (size_t)(row + 8) * ldc + col;
            *(float2*)c0 = make_float2(acc[mt][nt][0], acc[mt][nt][1]);
            *(float2*)c1 = make_float2(acc[mt][nt][2], acc[mt][nt][3]);
        }
    }
}

// ============================================================================
// High-throughput converts: 8 floats/thread, single uint4 (16B) store.
// ============================================================================
__device__ __forceinline__ void cvt8_store(const float* __restrict__ src,
                                           __half* __restrict__ dst,
                                           size_t i)
{
    const float4 v0 = *(const float4*)(src + i);
    const float4 v1 = *(const float4*)(src + i + 4);
    __half2 h0 = __floats2half2_rn(v0.x, v0.y);
    __half2 h1 = __floats2half2_rn(v0.z, v0.w);
    __half2 h2 = __floats2half2_rn(v1.x, v1.y);
    __half2 h3 = __floats2half2_rn(v1.z, v1.w);
    uint4 o;
    o.x = *(uint32_t*)&h0;
    o.y = *(uint32_t*)&h1;
    o.z = *(uint32_t*)&h2;
    o.w = *(uint32_t*)&h3;
    *(uint4*)(dst + i) = o;
}

__global__ __launch_bounds__(256) void cvt_x(const float* __restrict__ src,
                                             __half* __restrict__ dst)
{
    if (blockIdx.x == 0 && threadIdx.x == 0) {
        g_flag_count = 0;
        g_amb_count = 0;
        g_fix_delta = 0;
    }
    const size_t i = ((size_t)blockIdx.x * 256 + threadIdx.x) * 8;
    cvt8_store(src, dst, i);
}

__global__ __launch_bounds__(256) void cvt_w(
    const float* __restrict__ w1, __half* __restrict__ w1d,
    const float* __restrict__ w2, __half* __restrict__ w2d)
{
    const int half_grid = (int)gridDim.x >> 1;
    const bool second = blockIdx.x >= half_grid;
    const float* src = second ? w2 : w1;
    __half* dst = second ? w2d : w1d;
    const size_t i =
        ((size_t)(blockIdx.x - (second ? half_grid : 0)) * 256 + threadIdx.x) * 8;
    cvt8_store(src, dst, i);
}

// ============================================================================
// fixup_a: phase A only (butterfly dots, w in regs), 4 CTAs/SM; ambiguous
// neurons deferred to g_amb, confident decisions applied directly.
// ============================================================================
__global__ __launch_bounds__(256, 4) void fixup_a(
    const float* __restrict__ x, const float* __restrict__ w1)
{
    const unsigned int n = min(g_flag_count, (unsigned int)FLAG_CAP);
    const int lane = threadIdx.x & 31;
    const unsigned int warp = (blockIdx.x * 256 + threadIdx.x) >> 5;
    const unsigned int nwarps = (gridDim.x * 256) >> 5;
    int delta = 0;

    const float beta = (float)(1.0 - 1.0 / 20.0);
    const __half one  = __float2half(1.0f);
    const __half zero = __float2half(0.0f);

    for (unsigned int i = warp; i < n; i += nwarps) {
        const unsigned int idx = g_flags[i];
        const int    hid = (int)(idx & 2047u);
        const size_t bs  = idx >> 11;
        const size_t b   = bs >> 8;
        const size_t s   = bs & 255;
        const size_t bse = ((b * 4) * 256 + s) * 2048 + hid;
        const size_t ts  = 256UL * 2048UL;

        const float4* wrow = (const float4*)(w1 + (size_t)hid * 512);
        float w[16];
        #pragma unroll
        for (int j = 0; j < 4; j++) {
            const float4 wv = wrow[lane + j * 32];
            w[j * 4 + 0] = wv.x; w[j * 4 + 1] = wv.y;
            w[j * 4 + 2] = wv.z; w[j * 4 + 3] = wv.w;
        }

        float accs[4];
        #pragma unroll
        for (int t = 0; t < 4; t++) {
            const float4* xrow =
                (const float4*)(x + (((b * 4 + t) * 256 + s) << 9));
            float a = 0.0f;
            #pragma unroll
            for (int j = 0; j < 4; j++) {
                const float4 xv = xrow[lane + j * 32];
                a = fmaf(xv.x, w[j * 4 + 0], a);
                a = fmaf(xv.y, w[j * 4 + 1], a);
                a = fmaf(xv.z, w[j * 4 + 2], a);
                a = fmaf(xv.w, w[j * 4 + 3], a);
            }
            #pragma unroll
            for (int o = 16; o; o >>= 1)
                a += __shfl_xor_sync(0xFFFFFFFFu, a, o);
            accs[t] = a;
        }

        bool amb = false;
        {
            float v = 0.0f;
            #pragma unroll
            for (int t = 0; t < 4; t++) {
                v = fmaf(beta, v, accs[t]);
                amb |= (fabsf(v - 1.0f) < AMB_EPS);
                v = (v > 1.0f) ? 0.0f : v;
            }
        }

        if (lane == 0) {
            if (amb) {
                const unsigned int pos = atomicAdd(&g_amb_count, 1u);
                if (pos < AMB_CAP) g_amb[pos] = idx;
            } else {
                float v = 0.0f;
                #pragma unroll
                for (int t = 0; t < 4; t++) {
                    v = fmaf(beta, v, accs[t]);
                    const bool fire = (v > 1.0f);
                    const __half old = g_spk[bse + (size_t)t * ts];
                    const bool oldf = (__half2float(old) > 0.5f);
                    if (fire != oldf) {
                        g_spk[bse + (size_t)t * ts] = fire ? one : zero;
                        delta += fire ? 1 : -1;
                    }
                    v = fire ? 0.0f : v;
                }
            }
        }
    }

    #pragma unroll
    for (int o = 16; o; o >>= 1) delta += __shfl_down_sync(0xFFFFFFFFu, delta, o);
    __shared__ int wsum[8];
    if (lane == 0) wsum[threadIdx.x >> 5] = delta;
    __syncthreads();
    if (threadIdx.x == 0) {
        int tot = 0;
        #pragma unroll
        for (int w = 0; w < 8; w++) tot += wsum[w];
        if (tot != 0) atomicAdd(&g_fix_delta, tot);
    }
}

// ============================================================================
// fixup_b: exact sequential fp32 resolve for ambiguous neurons (rare).
// ============================================================================
__global__ __launch_bounds__(256) void fixup_b(
    const float* __restrict__ x, const float* __restrict__ w1)
{
    __shared__ float s_w[8][512];
    __shared__ float s_x[8][512];

    const unsigned int n = min(g_amb_count, (unsigned int)AMB_CAP);
    const int lane = threadIdx.x & 31;
    const int wib  = threadIdx.x >> 5;
    const unsigned int warp = (blockIdx.x * 256 + threadIdx.x) >> 5;
    const unsigned int nwarps = (gridDim.x * 256) >> 5;
    int delta = 0;

    const float beta = (float)(1.0 - 1.0 / 20.0);
    const __half one  = __float2half(1.0f);
    const __half zero = __float2half(0.0f);

    for (unsigned int i = warp; i < n; i += nwarps) {
        const unsigned int idx = g_amb[i];
        const int    hid = (int)(idx & 2047u);
        const size_t bs  = idx >> 11;
        const size_t b   = bs >> 8;
        const size_t s   = bs & 255;
        const size_t bse = ((b * 4) * 256 + s) * 2048 + hid;
        const size_t ts  = 256UL * 2048UL;

        const float4* wrow = (const float4*)(w1 + (size_t)hid * 512);
        #pragma unroll
        for (int j = 0; j < 4; j++)
            *(float4*)&s_w[wib][(lane + j * 32) * 4] = wrow[lane + j * 32];

        float accs[4];
        #pragma unroll
        for (int t = 0; t < 4; t++) {
            const float4* xrow =
                (const float4*)(x + (((b * 4 + t) * 256 + s) << 9));
            #pragma unroll
            for (int j = 0; j < 4; j++)
                *(float4*)&s_x[wib][(lane + j * 32) * 4] = xrow[lane + j * 32];
            __syncwarp();
            if (lane == 0) {
                float a = 0.0f;
                #pragma unroll 8
                for (int k = 0; k < 512; k++)
                    a = fmaf(s_x[wib][k], s_w[wib][k], a);
                accs[t] = a;
            }
            __syncwarp();
        }

        if (lane == 0) {
            float v = 0.0f;
            #pragma unroll
            for (int t = 0; t < 4; t++) {
                v = fmaf(beta, v, accs[t]);
                const bool fire = (v > 1.0f);
                const __half old = g_spk[bse + (size_t)t * ts];
                const bool oldf = (__half2float(old) > 0.5f);
                if (fire != oldf) {
                    g_spk[bse + (size_t)t * ts] = fire ? one : zero;
                    delta += fire ? 1 : -1;
                }
                v = fire ? 0.0f : v;
            }
        }
    }

    #pragma unroll
    for (int o = 16; o; o >>= 1) delta += __shfl_down_sync(0xFFFFFFFFu, delta, o);
    __shared__ int wsum[8];
    if (lane == 0) wsum[wib] = delta;
    __syncthreads();
    if (threadIdx.x == 0) {
        int tot = 0;
        #pragma unroll
        for (int w = 0; w < 8; w++) tot += wsum[w];
        if (tot != 0) atomicAdd(&g_fix_delta, tot);
    }
}

__global__ __launch_bounds__(1024) void rate_kernel(float* __restrict__ out_rate)
{
    long long s = 0;
    for (int i = threadIdx.x; i < 2048; i += 1024) s += g_partial[i];
    #pragma unroll
    for (int o = 16; o; o >>= 1) s += __shfl_down_sync(0xFFFFFFFFu, s, o);
    __shared__ long long sh[32];
    if ((threadIdx.x & 31) == 0) sh[threadIdx.x >> 5] = s;
    __syncthreads();
    if (threadIdx.x == 0) {
        long long tot = 0;
        #pragma unroll
        for (int w = 0; w < 32; w++) tot += sh[w];
        tot += g_fix_delta;
        *out_rate = (float)((double)tot / 33554432.0);
    }
}

// ============================================================================
extern "C" void kernel_launch(void* const* d_in, const int* in_sizes, int n_in,
                              void* d_out, int out_size)
{
    const float* x  = (const float*)d_in[0];
    const float* w1 = (const float*)d_in[1];
    const float* w2 = (const float*)d_in[2];
    float* out = (float*)d_out;

    __half *xh, *w1h, *w2h, *spk;
    cudaGetSymbolAddress((void**)&xh,  g_xh);
    cudaGetSymbolAddress((void**)&w1h, g_w1h);
    cudaGetSymbolAddress((void**)&w2h, g_w2h);
    cudaGetSymbolAddress((void**)&spk, g_spk);

    cudaFuncSetAttribute(gemm1_lif, cudaFuncAttributeMaxDynamicSharedMemorySize,
                         G1_SMEM_ALLOC);
    cudaFuncSetAttribute(gemm_f16, cudaFuncAttributeMaxDynamicSharedMemorySize,
                         G2_SMEM_ALLOC);

    // converts: 8 floats/thread
    cvt_x<<<4096, 256>>>(x, xh);
    cvt_w<<<1024, 256>>>(w1, w1h, w2, w2h);

    // GEMM1 + LIF fused (3-stage, 2 CTAs/SM)
    gemm1_lif<<<dim3(16, 128), 256, G1_SMEM_ALLOC>>>(xh, w1h);

    // phase A (high occupancy), phase B (rare exact resolves), rate
    fixup_a<<<1184, 256>>>(x, w1);
    fixup_b<<<256, 256>>>(x, w1);
    rate_kernel<<<1, 1024>>>(out + (out_size - 1));

    // GEMM2 on corrected spikes (3-stage, 2 CTAs/SM)
    gemm_f16<<<dim3(512 / BN, 16384 / BM), 256, G2_SMEM_ALLOC>>>(
        spk, w2h, out, 512, 2048 / BK, 2048, 2048);
}